// round 11
// baseline (speedup 1.0000x reference)
#include <cuda_runtime.h>
#include <cuda_fp16.h>
#include <math.h>
#include <stdint.h>

// ---------------- problem constants ----------------
static constexpr int BB=4096, D3=288, LZ=32, HH=512, OO=96, EE=8, GHD=128;
static constexpr int MBK = BB/128;   // 32 m-blocks (128-row blobs)

#define SWZ(o) ((o) ^ (((o) >> 3) & 0x70))

// ---------------- global scratch (no allocs allowed) ----------------
// int8 activation streams: [mblk][3P kb][128 rows x 128 bytes] (16KB blobs)
__device__ __align__(128) int8_t g_sA0[MBK*9*16384];
__device__ __align__(128) int8_t g_sA1[MBK*15*16384];
__device__ __align__(128) int8_t g_sA2[MBK*15*16384];
__device__ __align__(128) int8_t g_sA3[MBK*12*16384];
// int8 weight streams: [e][nblk][3P kb][64 rows x 128 bytes] (8KB blobs)
__device__ __align__(128) int8_t g_sW0[8*8*9*8192];
__device__ __align__(128) int8_t g_sW1[8*8*15*8192];
__device__ __align__(128) int8_t g_sW2[8*8*15*8192];
__device__ __align__(128) int8_t g_sW3[8*2*12*8192];
// scales
__device__ float g_al0[BB], g_al1[BB], g_al2[BB], g_al3[BB];
__device__ float g_be0[8*512], g_be1[8*512], g_be2[8*512], g_be3[8*128];
// f32 intermediates
__device__ float g_h1[BB*HH], g_h2[BB*HH], g_h3[BB*HH];
// fp16 gating path blobs
__device__ __align__(128) __half g_A0h[MBK*5*8192], g_A0l[MBK*5*8192];
__device__ __align__(128) __half g_G1h[MBK*2*8192], g_G1l[MBK*2*8192];
__device__ __align__(128) __half g_gW1h[2*5*4096],  g_gW1l[2*5*4096];
__device__ __align__(128) __half g_gW2h[2*2*4096],  g_gW2l[2*2*4096];
__device__ float g_gh2[BB*GHD];
__device__ float g_gate[BB*EE];

// ---------------- PTX helpers ----------------
__device__ __forceinline__ uint32_t smem_u32(const void* p) {
    uint32_t a;
    asm("{ .reg .u64 t; cvta.to.shared.u64 t, %1; cvt.u32.u64 %0, t; }" : "=r"(a) : "l"(p));
    return a;
}
__device__ __forceinline__ void mbar_init(uint32_t m, uint32_t c) {
    asm volatile("mbarrier.init.shared.b64 [%0], %1;" :: "r"(m), "r"(c) : "memory");
}
__device__ __forceinline__ void mbar_expect(uint32_t m, uint32_t b) {
    asm volatile("mbarrier.arrive.expect_tx.shared.b64 _, [%0], %1;" :: "r"(m), "r"(b) : "memory");
}
__device__ __forceinline__ void mbar_arrive(uint32_t m) {
    asm volatile("mbarrier.arrive.shared.b64 _, [%0];" :: "r"(m) : "memory");
}
__device__ __forceinline__ void mbar_wait(uint32_t m, uint32_t ph) {
    uint32_t done;
    asm volatile("{\n\t.reg .pred p;\n\t"
        "mbarrier.try_wait.parity.acquire.cta.shared::cta.b64 p, [%1], %2;\n\t"
        "selp.b32 %0, 1, 0, p;\n\t}" : "=r"(done) : "r"(m), "r"(ph) : "memory");
    while (!done) {
        asm volatile("{\n\t.reg .pred p;\n\t"
            "mbarrier.try_wait.parity.acquire.cta.shared::cta.b64 p, [%1], %2, 0x989680;\n\t"
            "selp.b32 %0, 1, 0, p;\n\t}" : "=r"(done) : "r"(m), "r"(ph) : "memory");
    }
}
__device__ __forceinline__ void bulk_g2s(uint32_t dst, const void* src, uint32_t bytes, uint32_t mbar) {
    asm volatile("cp.async.bulk.shared::cluster.global.mbarrier::complete_tx::bytes [%0], [%1], %2, [%3];"
        :: "r"(dst), "l"(src), "r"(bytes), "r"(mbar) : "memory");
}
__device__ __forceinline__ void ldm_x4(uint32_t* r, uint32_t addr) {
    asm volatile("ldmatrix.sync.aligned.m8n8.x4.shared.b16 {%0,%1,%2,%3}, [%4];"
        : "=r"(r[0]), "=r"(r[1]), "=r"(r[2]), "=r"(r[3]) : "r"(addr));
}
__device__ __forceinline__ void mma16816(float* d, const uint32_t* a, uint32_t b0, uint32_t b1) {
    asm("mma.sync.aligned.m16n8k16.row.col.f32.f16.f16.f32 "
        "{%0,%1,%2,%3}, {%4,%5,%6,%7}, {%8,%9}, {%0,%1,%2,%3};"
        : "+f"(d[0]), "+f"(d[1]), "+f"(d[2]), "+f"(d[3])
        : "r"(a[0]), "r"(a[1]), "r"(a[2]), "r"(a[3]), "r"(b0), "r"(b1));
}
__device__ __forceinline__ void imma16832(int* d, const uint32_t* a, uint32_t b0, uint32_t b1) {
    asm("mma.sync.aligned.m16n8k32.row.col.s32.s8.s8.s32 "
        "{%0,%1,%2,%3}, {%4,%5,%6,%7}, {%8,%9}, {%0,%1,%2,%3};"
        : "+r"(d[0]), "+r"(d[1]), "+r"(d[2]), "+r"(d[3])
        : "r"(a[0]), "r"(a[1]), "r"(a[2]), "r"(a[3]), "r"(b0), "r"(b1));
}
// Exact int->float for |p| < 2^22 via magic number (IADD+FADD, avoids slow I2F).
__device__ __forceinline__ float i2f_fast(int p) {
    return __int_as_float((uint32_t)(p + 0x4B400000)) - 12582912.f;
}
__device__ __forceinline__ float elu1(float x) { return x > 0.f ? x : expm1f(x); }

// ================= int8 blended expert GEMM =================
// A stream per row: [a1 | a1 | a2] (3P kb of 128 int8); W stream per out-col: [w1 | w2 | w1].
// A = (a1 + a2/256)*alpha, W = (w1 + w2/256)*beta (alpha=beta=max/127).
// result += alpha*beta*(S_seg1 + (S_seg2 + S_seg3)/256); gate+dequant fused per (kb,e).
template<int MW, bool ACT>
__global__ void __launch_bounds__(32*(MW*2+1), 1) moe_i8(
    const int8_t* __restrict__ As, int kbtot, int P,
    const int8_t* __restrict__ Ws, int wnb,
    const float* __restrict__ alpha, const float* __restrict__ beta,
    const float* __restrict__ bias, const float* __restrict__ gate, int ntot,
    float* __restrict__ C, int ldc)
{
    constexpr int CW = MW * 2;
    constexpr int NT = 32 * (CW + 1);
    constexpr int BM = MW * 32;
    constexpr int ABYTES = BM * 128;
    constexpr int W_OFFc = 2 * ABYTES;
    constexpr int GS_OFFc = W_OFFc + 8 * 8192;
    constexpr int BE_OFFc = GS_OFFc + BM * EE * 4;
    constexpr int BI_OFFc = BE_OFFc + 2048;
    constexpr int BAR_OFFc = BI_OFFc + 2048;

    extern __shared__ __align__(1024) uint8_t smem[];
    const uint32_t sb = smem_u32(smem);
    const int tid = threadIdx.x;
    const int lane = tid & 31, wid = tid >> 5;
    const int wm = wid % MW, wn = (wid / MW) & 1;
    const int mblk = blockIdx.y, nblk = blockIdx.x;

    const uint32_t bAf = sb + BAR_OFFc;
    const uint32_t bAe = sb + BAR_OFFc + 16;
    const uint32_t bWf = sb + BAR_OFFc + 32;
    const uint32_t bWe = sb + BAR_OFFc + 96;

    if (tid == 0) {
        for (int s = 0; s < 2; s++) { mbar_init(bAf + s*8, 1); mbar_init(bAe + s*8, CW); }
        for (int s = 0; s < 8; s++) { mbar_init(bWf + s*8, 1); mbar_init(bWe + s*8, CW); }
    }

    float* gS  = (float*)(smem + GS_OFFc);
    float* beS = (float*)(smem + BE_OFFc);
    float* biS = (float*)(smem + BI_OFFc);
    for (int i = tid; i < BM * EE; i += NT) gS[i] = gate[(size_t)mblk * BM * EE + i];
    for (int i = tid; i < EE * 64; i += NT) {
        int e = i >> 6, j = i & 63;
        beS[i] = beta[e * (wnb * 64) + nblk * 64 + j];
        int o = nblk * 64 + j;
        biS[i] = (o < ntot) ? bias[e * ntot + o] : 0.f;
    }
    __syncthreads();

    if (wid == CW) {
        if (lane == 0) {
            for (int kb = 0; kb < kbtot; kb++) {
                int as = kb & 1;
                if (kb >= 2) mbar_wait(bAe + as*8, ((kb >> 1) & 1) ^ 1);
                mbar_expect(bAf + as*8, ABYTES);
                size_t aoff;
                if (MW == 4) aoff = ((size_t)mblk * kbtot + kb) * 16384;
                else         aoff = ((size_t)(mblk >> 1) * kbtot + kb) * 16384 + (size_t)(mblk & 1) * 8192;
                bulk_g2s(sb + as*ABYTES, As + aoff, ABYTES, bAf + as*8);
                for (int e = 0; e < EE; e++) {
                    int wu = kb * EE + e, s = wu & 7;
                    if (wu >= 8) mbar_wait(bWe + s*8, ((wu >> 3) & 1) ^ 1);
                    mbar_expect(bWf + s*8, 8192);
                    size_t woff = (((size_t)e * wnb + nblk) * kbtot + kb) * 8192;
                    bulk_g2s(sb + W_OFFc + s*8192, Ws + woff, 8192, bWf + s*8);
                }
            }
        }
        return;
    }

    // compute warps
    uint32_t offA[2][4], offB[2][4];
#pragma unroll
    for (int i = 0; i < 2; i++)
#pragma unroll
        for (int j = 0; j < 4; j++)
            offA[i][j] = SWZ((uint32_t)((wm*32 + i*16 + (lane & 15)) * 128 + j*32 + (lane >> 4) * 16));
#pragma unroll
    for (int p = 0; p < 2; p++)
#pragma unroll
        for (int j = 0; j < 4; j++)
            offB[p][j] = SWZ((uint32_t)((wn*32 + p*16 + (lane & 15)) * 128 + j*32 + (lane >> 4) * 16));

    const int r0 = wm*32 + (lane >> 2);
    const int cbase = wn*32 + (lane & 3) * 2;
    float alp[2][2];
#pragma unroll
    for (int i = 0; i < 2; i++)
#pragma unroll
        for (int h = 0; h < 2; h++)
            alp[i][h] = alpha[mblk*BM + r0 + i*16 + h*8];

    float acc[2][4][4];
#pragma unroll
    for (int i = 0; i < 2; i++)
#pragma unroll
        for (int n8 = 0; n8 < 4; n8++)
#pragma unroll
            for (int q = 0; q < 4; q++) acc[i][n8][q] = 0.f;

#pragma unroll 1
    for (int kb = 0; kb < kbtot; kb++) {
        int as = kb & 1;
        mbar_wait(bAf + as*8, (kb >> 1) & 1);
        const uint32_t Ab = sb + as*ABYTES;
        uint32_t aF[2][4][4];
#pragma unroll
        for (int i = 0; i < 2; i++)
#pragma unroll
            for (int j = 0; j < 4; j++) ldm_x4(aF[i][j], Ab + offA[i][j]);
        if (lane == 0) mbar_arrive(bAe + as*8);

        float kbsc = (kb < P) ? 1.f : (1.f/256.f);
        float ral[2][2];
#pragma unroll
        for (int i = 0; i < 2; i++) { ral[i][0] = alp[i][0]*kbsc; ral[i][1] = alp[i][1]*kbsc; }

#pragma unroll 1
        for (int e = 0; e < EE; e++) {
            int wu = kb * EE + e, s = wu & 7;
            mbar_wait(bWf + s*8, (wu >> 3) & 1);
            const uint32_t Wb = sb + W_OFFc + s*8192;
            int part[2][4][4];
#pragma unroll
            for (int i = 0; i < 2; i++)
#pragma unroll
                for (int n8 = 0; n8 < 4; n8++)
#pragma unroll
                    for (int q = 0; q < 4; q++) part[i][n8][q] = 0;
#pragma unroll
            for (int j = 0; j < 4; j++) {
                uint32_t b0[4], b1[4];
                ldm_x4(b0, Wb + offB[0][j]);
                ldm_x4(b1, Wb + offB[1][j]);
#pragma unroll
                for (int i = 0; i < 2; i++)
#pragma unroll
                    for (int n8 = 0; n8 < 4; n8++) {
                        const uint32_t* bp = (n8 < 2) ? b0 : b1;
                        int q = n8 & 1;
                        imma16832(part[i][n8], aF[i][j], bp[q], bp[2 + q]);
                    }
            }
            if (lane == 0) mbar_arrive(bWe + s*8);
            // fused gate + dequant (magic-number conversion: IADD+FADD, no I2F)
            float rf[2][2];
#pragma unroll
            for (int i = 0; i < 2; i++) {
                rf[i][0] = gS[(r0 + i*16    ) * EE + e] * ral[i][0];
                rf[i][1] = gS[(r0 + i*16 + 8) * EE + e] * ral[i][1];
            }
#pragma unroll
            for (int n8 = 0; n8 < 4; n8++) {
                int cl = cbase + n8*8;
                float bc0 = beS[e*64 + cl], bc1 = beS[e*64 + cl + 1];
#pragma unroll
                for (int i = 0; i < 2; i++) {
                    acc[i][n8][0] += rf[i][0] * (bc0 * i2f_fast(part[i][n8][0]));
                    acc[i][n8][1] += rf[i][0] * (bc1 * i2f_fast(part[i][n8][1]));
                    acc[i][n8][2] += rf[i][1] * (bc0 * i2f_fast(part[i][n8][2]));
                    acc[i][n8][3] += rf[i][1] * (bc1 * i2f_fast(part[i][n8][3]));
                }
            }
        }
    }

    // epilogue: blended bias + activation + f32 store
#pragma unroll
    for (int i = 0; i < 2; i++) {
#pragma unroll
        for (int h = 0; h < 2; h++) {
            int lr = r0 + i*16 + h*8;
            int grow = mblk*BM + lr;
#pragma unroll
            for (int n8 = 0; n8 < 4; n8++) {
                int cl = cbase + n8*8;
                float v0 = acc[i][n8][h*2 + 0];
                float v1 = acc[i][n8][h*2 + 1];
                float s0 = 0.f, s1 = 0.f;
#pragma unroll
                for (int e = 0; e < EE; e++) {
                    float g = gS[lr * EE + e];
                    s0 += g * biS[e*64 + cl];
                    s1 += g * biS[e*64 + cl + 1];
                }
                v0 += s0; v1 += s1;
                if (ACT) { v0 = elu1(v0); v1 = elu1(v1); }
                int c = nblk*64 + cl;
                if (c < ntot)     C[(size_t)grow * ldc + c]     = v0;
                if (c + 1 < ntot) C[(size_t)grow * ldc + c + 1] = v1;
            }
        }
    }
}

// ================= int8 quantize kernels =================
template<int P>
__global__ void quant_act(const float* __restrict__ src, int lda, int K1,
                          const float* __restrict__ z, int K,
                          int8_t* __restrict__ st, float* __restrict__ alpha)
{
    int r = (blockIdx.x * blockDim.x + threadIdx.x) >> 5;
    int lane = threadIdx.x & 31;
    if (r >= BB) return;
    float v[P][4];
    float mx = 0.f;
#pragma unroll
    for (int ch = 0; ch < P; ch++) {
#pragma unroll
        for (int q = 0; q < 4; q++) {
            int c = ch*128 + lane*4 + q;
            float val = 0.f;
            if (c < K1) val = src[(size_t)r * lda + c];
            else if (c < K) val = z[(size_t)r * LZ + (c - K1)];
            v[ch][q] = val;
            mx = fmaxf(mx, fabsf(val));
        }
    }
#pragma unroll
    for (int o = 16; o; o >>= 1) mx = fmaxf(mx, __shfl_xor_sync(0xffffffffu, mx, o));
    if (mx == 0.f) mx = 1.f;
    float qs = 127.f / mx, inv = mx / 127.f, qs2 = qs * 256.f;
    if (lane == 0) alpha[r] = inv;
    int mb = r >> 7, rin = r & 127;
    int8_t* base = st + (size_t)mb * (3*P) * 16384;
    uint32_t sw = SWZ((uint32_t)(rin*128 + lane*4));
#pragma unroll
    for (int ch = 0; ch < P; ch++) {
        uint32_t w1 = 0, w2 = 0;
#pragma unroll
        for (int q = 0; q < 4; q++) {
            float val = v[ch][q];
            int a1 = __float2int_rn(val * qs);
            float res = fmaf((float)a1, -inv, val);
            int a2 = __float2int_rn(res * qs2);
            a2 = a2 > 127 ? 127 : (a2 < -127 ? -127 : a2);
            w1 |= ((uint32_t)(uint8_t)(int8_t)a1) << (8*q);
            w2 |= ((uint32_t)(uint8_t)(int8_t)a2) << (8*q);
        }
        *(uint32_t*)(base + (size_t)(ch        )*16384 + sw) = w1;
        *(uint32_t*)(base + (size_t)(P + ch    )*16384 + sw) = w1;
        *(uint32_t*)(base + (size_t)(2*P + ch  )*16384 + sw) = w2;
    }
}

template<int P>
__global__ void quant_w(const float* __restrict__ W, int N, int K, int nblks,
                        int8_t* __restrict__ st, float* __restrict__ beta)
{
    int t = (blockIdx.x * blockDim.x + threadIdx.x) >> 5;
    int lane = threadIdx.x & 31;
    int tot = EE * nblks * 64;
    if (t >= tot) return;
    int e = t / (nblks * 64), col = t % (nblks * 64);
    const float* src = W + ((size_t)e * N + col) * K;
    float v[P][4];
    float mx = 0.f;
#pragma unroll
    for (int ch = 0; ch < P; ch++) {
#pragma unroll
        for (int q = 0; q < 4; q++) {
            int c = ch*128 + lane*4 + q;
            float val = (col < N && c < K) ? src[c] : 0.f;
            v[ch][q] = val;
            mx = fmaxf(mx, fabsf(val));
        }
    }
#pragma unroll
    for (int o = 16; o; o >>= 1) mx = fmaxf(mx, __shfl_xor_sync(0xffffffffu, mx, o));
    if (mx == 0.f) mx = 1.f;
    float qs = 127.f / mx, inv = mx / 127.f, qs2 = qs * 256.f;
    if (lane == 0) beta[e * (nblks*64) + col] = inv;
    int nb = col >> 6, rin = col & 63;
    int8_t* base = st + ((size_t)(e * nblks + nb) * (3*P)) * 8192;
    uint32_t sw = SWZ((uint32_t)(rin*128 + lane*4));
#pragma unroll
    for (int ch = 0; ch < P; ch++) {
        uint32_t w1 = 0, w2 = 0;
#pragma unroll
        for (int q = 0; q < 4; q++) {
            float val = v[ch][q];
            int a1 = __float2int_rn(val * qs);
            float res = fmaf((float)a1, -inv, val);
            int a2 = __float2int_rn(res * qs2);
            a2 = a2 > 127 ? 127 : (a2 < -127 ? -127 : a2);
            w1 |= ((uint32_t)(uint8_t)(int8_t)a1) << (8*q);
            w2 |= ((uint32_t)(uint8_t)(int8_t)a2) << (8*q);
        }
        *(uint32_t*)(base + (size_t)(ch      )*8192 + sw) = w1;  // seg1: w1
        *(uint32_t*)(base + (size_t)(P + ch  )*8192 + sw) = w2;  // seg2: w2 (x a1)
        *(uint32_t*)(base + (size_t)(2*P + ch)*8192 + sw) = w1;  // seg3: w1 (x a2)
    }
}

// ================= fp16 gating GEMM (3-term split) =================
template<int MW, int EXP, bool GATE, bool ACT, bool OUTF32>
__global__ void __launch_bounds__(32*(MW*2+1), 1) moe_gemm(
    const __half* __restrict__ Ah, const __half* __restrict__ Al, int kblks,
    const __half* __restrict__ Wh, const __half* __restrict__ Wl, int wnb,
    const float* __restrict__ bias, const float* __restrict__ gate, int ntot,
    __half* __restrict__ Oh, __half* __restrict__ Ol, int okb,
    float* __restrict__ C, int ldc)
{
    constexpr int CW = MW * 2;
    constexpr int NT = 32 * (CW + 1);
    constexpr int BM = MW * 32;
    constexpr int ABYTES = BM * 128;
    constexpr int A_STG  = 2 * ABYTES;
    constexpr int W_OFFc = 2 * A_STG;
    constexpr int W_STRIDE = 16384;
    constexpr int GS_OFFc  = W_OFFc + 8 * W_STRIDE;
    constexpr int BS_OFFc  = GS_OFFc + 4096;
    constexpr int BAR_OFFc = BS_OFFc + 2048;

    extern __shared__ __align__(1024) uint8_t smem[];
    const uint32_t sb = smem_u32(smem);
    const int tid = threadIdx.x;
    const int lane = tid & 31, wid = tid >> 5;
    const int wm = wid % MW, wn = (wid / MW) & 1;
    const int mblk = blockIdx.y, nblk = blockIdx.x;

    const uint32_t bAf = sb + BAR_OFFc;
    const uint32_t bAe = sb + BAR_OFFc + 16;
    const uint32_t bWf = sb + BAR_OFFc + 32;
    const uint32_t bWe = sb + BAR_OFFc + 96;

    if (tid == 0) {
        for (int s = 0; s < 2; s++) { mbar_init(bAf + s*8, 1); mbar_init(bAe + s*8, CW); }
        for (int s = 0; s < 8; s++) { mbar_init(bWf + s*8, 1); mbar_init(bWe + s*8, CW); }
    }
    float* gS = (float*)(smem + GS_OFFc);
    float* bS = (float*)(smem + BS_OFFc);
    if (GATE) {
        for (int i = tid; i < BM * EE; i += NT) gS[i] = gate[(size_t)mblk * BM * EE + i];
    }
    for (int i = tid; i < EXP * 64; i += NT) {
        int e = i >> 6, j = i & 63, o = nblk * 64 + j;
        bS[i] = (o < ntot) ? bias[e * ntot + o] : 0.f;
    }
    __syncthreads();

    if (wid == CW) {
        if (lane == 0) {
            for (int kb = 0; kb < kblks; kb++) {
                int as = kb & 1;
                if (kb >= 2) mbar_wait(bAe + as*8, ((kb >> 1) & 1) ^ 1);
                mbar_expect(bAf + as*8, 2 * ABYTES);
                size_t aoff;
                if (MW == 4) aoff = ((size_t)mblk * kblks + kb) * 8192;
                else         aoff = ((size_t)(mblk >> 1) * kblks + kb) * 8192 + (size_t)(mblk & 1) * 4096;
                bulk_g2s(sb + as*A_STG,          Ah + aoff, ABYTES, bAf + as*8);
                bulk_g2s(sb + as*A_STG + ABYTES, Al + aoff, ABYTES, bAf + as*8);
                for (int e = 0; e < EXP; e++) {
                    int wu = kb * EXP + e, s = wu & 7;
                    if (wu >= 8) mbar_wait(bWe + s*8, ((wu >> 3) & 1) ^ 1);
                    mbar_expect(bWf + s*8, 16384);
                    size_t woff = (((size_t)e * wnb + nblk) * kblks + kb) * 4096;
                    bulk_g2s(sb + W_OFFc + s*W_STRIDE,        Wh + woff, 8192, bWf + s*8);
                    bulk_g2s(sb + W_OFFc + s*W_STRIDE + 8192, Wl + woff, 8192, bWf + s*8);
                }
            }
        }
        return;
    }

    uint32_t offA[2][4], offB[2][4];
#pragma unroll
    for (int i = 0; i < 2; i++)
#pragma unroll
        for (int j = 0; j < 4; j++)
            offA[i][j] = SWZ((uint32_t)((wm*32 + i*16 + (lane & 15)) * 128 + j*32 + (lane >> 4) * 16));
#pragma unroll
    for (int p = 0; p < 2; p++)
#pragma unroll
        for (int j = 0; j < 4; j++)
            offB[p][j] = SWZ((uint32_t)((wn*32 + p*16 + (lane & 15)) * 128 + j*32 + (lane >> 4) * 16));

    float acc[2][4][4];
#pragma unroll
    for (int i = 0; i < 2; i++)
#pragma unroll
        for (int n8 = 0; n8 < 4; n8++)
#pragma unroll
            for (int q = 0; q < 4; q++) acc[i][n8][q] = 0.f;

    int wu = 0;
#pragma unroll 1
    for (int kb = 0; kb < kblks; kb++) {
        int as = kb & 1;
        mbar_wait(bAf + as*8, (kb >> 1) & 1);
        const uint32_t Ab = sb + as*A_STG;
        uint32_t aH[2][4][4], aL[2][4][4];
#pragma unroll
        for (int i = 0; i < 2; i++)
#pragma unroll
            for (int j = 0; j < 4; j++) {
                ldm_x4(aH[i][j], Ab + offA[i][j]);
                ldm_x4(aL[i][j], Ab + ABYTES + offA[i][j]);
            }
        if (lane == 0) mbar_arrive(bAe + as*8);
#pragma unroll 1
        for (int e = 0; e < EXP; e++) {
            int s = wu & 7;
            mbar_wait(bWf + s*8, (wu >> 3) & 1);
            const uint32_t Wb = sb + W_OFFc + s*W_STRIDE;
#pragma unroll
            for (int j = 0; j < 4; j++) {
                uint32_t b0h[4], b1h[4], b0l[4], b1l[4];
                ldm_x4(b0h, Wb + offB[0][j]);
                ldm_x4(b1h, Wb + offB[1][j]);
                ldm_x4(b0l, Wb + 8192 + offB[0][j]);
                ldm_x4(b1l, Wb + 8192 + offB[1][j]);
#pragma unroll
                for (int i = 0; i < 2; i++)
#pragma unroll
                    for (int n8 = 0; n8 < 4; n8++) {
                        const uint32_t* bh = (n8 < 2) ? b0h : b1h;
                        const uint32_t* bl = (n8 < 2) ? b0l : b1l;
                        int q = n8 & 1;
                        mma16816(acc[i][n8], aH[i][j], bh[q], bh[2 + q]);
                        mma16816(acc[i][n8], aL[i][j], bh[q], bh[2 + q]);
                        mma16816(acc[i][n8], aH[i][j], bl[q], bl[2 + q]);
                    }
            }
            if (lane == 0) mbar_arrive(bWe + s*8);
            wu++;
        }
    }

    const int rbase = wm*32 + (lane >> 2);
    const int cbase = wn*32 + (lane & 3) * 2;
#pragma unroll
    for (int i = 0; i < 2; i++) {
#pragma unroll
        for (int hf = 0; hf < 2; hf++) {
            int lr = rbase + i*16 + hf*8;
            int gr = mblk*BM + lr;
#pragma unroll
            for (int n8 = 0; n8 < 4; n8++) {
                int cl = cbase + n8*8;
                float v0 = acc[i][n8][hf*2 + 0] + bS[cl];
                float v1 = acc[i][n8][hf*2 + 1] + bS[cl + 1];
                if (ACT) { v0 = elu1(v0); v1 = elu1(v1); }
                if (OUTF32) {
                    int c = nblk*64 + cl;
                    if (c < ntot)     C[(size_t)gr * ldc + c]     = v0;
                    if (c + 1 < ntot) C[(size_t)gr * ldc + c + 1] = v1;
                } else {
                    __half h0 = __float2half_rn(v0), h1 = __float2half_rn(v1);
                    __half l0 = __float2half_rn(v0 - __half2float(h0));
                    __half l1 = __float2half_rn(v1 - __half2float(h1));
                    int gcol = nblk*64 + cl;
                    int blobm = gr >> 7, rin = gr & 127;
                    uint32_t off = SWZ((uint32_t)(rin * 128 + (gcol & 63) * 2));
                    size_t bidx = ((size_t)blobm * okb + (gcol >> 6)) * 8192;
                    *(__half2*)((uint8_t*)(Oh + bidx) + off) = __halves2half2(h0, h1);
                    *(__half2*)((uint8_t*)(Ol + bidx) + off) = __halves2half2(l0, l1);
                }
            }
        }
    }
}

// ---------------- fp16 prepack (gating weights + A0 blobs) ----------------
__device__ __forceinline__ void split_store(uint8_t* bh, uint8_t* bl, uint32_t sw, float4 v) {
    float vv[4] = {v.x, v.y, v.z, v.w};
    uint32_t h[4], l[4];
#pragma unroll
    for (int q = 0; q < 4; q++) {
        __half hh = __float2half_rn(vv[q]);
        __half ll = __float2half_rn(vv[q] - __half2float(hh));
        h[q] = (uint32_t)__half_as_ushort(hh);
        l[q] = (uint32_t)__half_as_ushort(ll);
    }
    *(uint2*)(bh + sw) = make_uint2(h[0] | (h[1] << 16), h[2] | (h[3] << 16));
    *(uint2*)(bl + sw) = make_uint2(l[0] | (l[1] << 16), l[2] | (l[3] << 16));
}

__global__ void prepack_w(const float* __restrict__ W, __half* __restrict__ Dh, __half* __restrict__ Dl,
                          int N, int K, int nblks, int kblks) {
    int t = blockIdx.x;
    int kb = t % kblks, nb = (t / kblks) % nblks;
    const float* src = W;
    uint8_t* bh = (uint8_t*)(Dh + (size_t)t * 4096);
    uint8_t* bl = (uint8_t*)(Dl + (size_t)t * 4096);
    for (int i = threadIdx.x; i < 1024; i += 256) {
        int r = i >> 4, c4 = i & 15;
        int n = nb * 64 + r, k = kb * 64 + c4 * 4;
        float4 v = make_float4(0.f, 0.f, 0.f, 0.f);
        if (n < N && k < K) v = *(const float4*)(src + (size_t)n * K + k);
        split_store(bh, bl, SWZ((uint32_t)(r * 128 + c4 * 8)), v);
    }
}

__global__ void prepack_a0(const float* __restrict__ x, const float* __restrict__ z) {
    int t = blockIdx.x;              // mblk*5 + kb
    int kb = t % 5, mb = t / 5;
    uint8_t* bh = (uint8_t*)(g_A0h + (size_t)t * 8192);
    uint8_t* bl = (uint8_t*)(g_A0l + (size_t)t * 8192);
    for (int i = threadIdx.x; i < 2048; i += 256) {
        int r = i >> 4, c4 = i & 15;
        int row = mb * 128 + r, k = kb * 64 + c4 * 4;
        float4 v;
        if (k < D3) v = *(const float4*)(x + (size_t)row * D3 + k);
        else        v = *(const float4*)(z + (size_t)row * LZ + (k - D3));
        split_store(bh, bl, SWZ((uint32_t)(r * 128 + c4 * 8)), v);
    }
}

// ---------------- gating logits + softmax over E=8 ----------------
__global__ void logits_softmax(const float* __restrict__ h2,
                               const float* __restrict__ gW3,
                               const float* __restrict__ gb3) {
    int tid = blockIdx.x * blockDim.x + threadIdx.x;
    int row = tid >> 3, e = tid & 7;
    if (row >= BB) return;
    float s = gb3[e];
    const float* hr = h2 + (size_t)row * GHD;
    const float* wr = gW3 + (size_t)e * GHD;
#pragma unroll 8
    for (int i = 0; i < GHD; i++) s += hr[i] * wr[i];
    float m = s;
#pragma unroll
    for (int o = 4; o; o >>= 1) m = fmaxf(m, __shfl_xor_sync(0xffffffffu, m, o));
    float ex = expf(s - m);
    float sum = ex;
#pragma unroll
    for (int o = 4; o; o >>= 1) sum += __shfl_xor_sync(0xffffffffu, sum, o);
    g_gate[tid] = ex / sum;
}

// ---------------- host ----------------
static constexpr int SMEMF_MW2 = 2*2*(64*128) + 8*16384 + 4096 + 2048 + 256;           // fp16 MW2
static constexpr int SMEMI_MW4 = 2*(128*128) + 8*8192 + 128*EE*4 + 2048 + 2048 + 256;  // int8 MW4
static constexpr int SMEMI_MW2 = 2*(64*128)  + 8*8192 + 64*EE*4  + 2048 + 2048 + 256;  // int8 MW2

extern "C" void kernel_launch(void* const* d_in, const int* in_sizes, int n_in,
                              void* d_out, int out_size) {
    const float* x   = (const float*)d_in[0];
    const float* z   = (const float*)d_in[1];
    const float* W0  = (const float*)d_in[2];
    const float* b0  = (const float*)d_in[3];
    const float* W1  = (const float*)d_in[4];
    const float* b1  = (const float*)d_in[5];
    const float* W2  = (const float*)d_in[6];
    const float* b2  = (const float*)d_in[7];
    const float* W3  = (const float*)d_in[8];
    const float* b3  = (const float*)d_in[9];
    const float* gW1 = (const float*)d_in[10];
    const float* gb1 = (const float*)d_in[11];
    const float* gW2 = (const float*)d_in[12];
    const float* gb2 = (const float*)d_in[13];
    const float* gW3 = (const float*)d_in[14];
    const float* gb3 = (const float*)d_in[15];
    float* out = (float*)d_out;
    (void)in_sizes; (void)n_in; (void)out_size;

    int8_t *sA0,*sA1,*sA2,*sA3,*sW0,*sW1,*sW2,*sW3;
    float *al0,*al1,*al2,*al3,*be0,*be1,*be2,*be3,*h1,*h2,*h3;
    __half *A0h,*A0l,*G1h,*G1l,*pg1h,*pg1l,*pg2h,*pg2l;
    float *gh2, *gate;
    cudaGetSymbolAddress((void**)&sA0, g_sA0); cudaGetSymbolAddress((void**)&sA1, g_sA1);
    cudaGetSymbolAddress((void**)&sA2, g_sA2); cudaGetSymbolAddress((void**)&sA3, g_sA3);
    cudaGetSymbolAddress((void**)&sW0, g_sW0); cudaGetSymbolAddress((void**)&sW1, g_sW1);
    cudaGetSymbolAddress((void**)&sW2, g_sW2); cudaGetSymbolAddress((void**)&sW3, g_sW3);
    cudaGetSymbolAddress((void**)&al0, g_al0); cudaGetSymbolAddress((void**)&al1, g_al1);
    cudaGetSymbolAddress((void**)&al2, g_al2); cudaGetSymbolAddress((void**)&al3, g_al3);
    cudaGetSymbolAddress((void**)&be0, g_be0); cudaGetSymbolAddress((void**)&be1, g_be1);
    cudaGetSymbolAddress((void**)&be2, g_be2); cudaGetSymbolAddress((void**)&be3, g_be3);
    cudaGetSymbolAddress((void**)&h1, g_h1);   cudaGetSymbolAddress((void**)&h2, g_h2);
    cudaGetSymbolAddress((void**)&h3, g_h3);
    cudaGetSymbolAddress((void**)&A0h, g_A0h); cudaGetSymbolAddress((void**)&A0l, g_A0l);
    cudaGetSymbolAddress((void**)&G1h, g_G1h); cudaGetSymbolAddress((void**)&G1l, g_G1l);
    cudaGetSymbolAddress((void**)&pg1h, g_gW1h); cudaGetSymbolAddress((void**)&pg1l, g_gW1l);
    cudaGetSymbolAddress((void**)&pg2h, g_gW2h); cudaGetSymbolAddress((void**)&pg2l, g_gW2l);
    cudaGetSymbolAddress((void**)&gh2, g_gh2); cudaGetSymbolAddress((void**)&gate, g_gate);

    cudaFuncSetAttribute(moe_gemm<2,1,false,true,false>, cudaFuncAttributeMaxDynamicSharedMemorySize, SMEMF_MW2);
    cudaFuncSetAttribute(moe_gemm<2,1,false,true,true>,  cudaFuncAttributeMaxDynamicSharedMemorySize, SMEMF_MW2);
    cudaFuncSetAttribute(moe_i8<4,true>,  cudaFuncAttributeMaxDynamicSharedMemorySize, SMEMI_MW4);
    cudaFuncSetAttribute(moe_i8<2,false>, cudaFuncAttributeMaxDynamicSharedMemorySize, SMEMI_MW2);

    // prepack: fp16 gating weights + A0 blobs; int8 weight streams; int8 x-stream
    prepack_w<<<10, 256>>>(gW1, pg1h, pg1l, GHD, 320, 2, 5);
    prepack_w<<<4,  256>>>(gW2, pg2h, pg2l, GHD, GHD, 2, 2);
    prepack_a0<<<160, 256>>>(x, z);
    quant_w<3><<<512, 256>>>(W0, HH, 320, 8, sW0, be0);
    quant_w<5><<<512, 256>>>(W1, HH, 544, 8, sW1, be1);
    quant_w<5><<<512, 256>>>(W2, HH, 544, 8, sW2, be2);
    quant_w<4><<<128, 256>>>(W3, OO, 512, 2, sW3, be3);
    quant_act<3><<<512, 256>>>(x, D3, D3, z, 320, sA0, al0);

    // gating MLP (fp16 path)
    moe_gemm<2,1,false,true,false><<<dim3(2, 64), 160, SMEMF_MW2>>>(
        A0h, A0l, 5, pg1h, pg1l, 2, gb1, nullptr, GHD, G1h, G1l, 2, nullptr, 0);
    moe_gemm<2,1,false,true,true><<<dim3(2, 64), 160, SMEMF_MW2>>>(
        G1h, G1l, 2, pg2h, pg2l, 2, gb2, nullptr, GHD, nullptr, nullptr, 0, gh2, GHD);
    logits_softmax<<<BB*EE/256, 256>>>(gh2, gW3, gb3);

    // blended expert layers (int8, magic-number dequant)
    moe_i8<4,true><<<dim3(8, 32), 288, SMEMI_MW4>>>(sA0, 9, 3, sW0, 8, al0, be0, b0, gate, HH, h1, HH);
    quant_act<5><<<512, 256>>>(h1, HH, HH, z, 544, sA1, al1);
    moe_i8<4,true><<<dim3(8, 32), 288, SMEMI_MW4>>>(sA1, 15, 5, sW1, 8, al1, be1, b1, gate, HH, h2, HH);
    quant_act<5><<<512, 256>>>(h2, HH, HH, z, 544, sA2, al2);
    moe_i8<4,true><<<dim3(8, 32), 288, SMEMI_MW4>>>(sA2, 15, 5, sW2, 8, al2, be2, b2, gate, HH, h3, HH);
    quant_act<4><<<512, 256>>>(h3, HH, HH, nullptr, 512, sA3, al3);
    moe_i8<2,false><<<dim3(2, 64), 160, SMEMI_MW2>>>(sA3, 12, 4, sW3, 2, al3, be3, b3, gate, OO, out, OO);
}

// round 12
// speedup vs baseline: 3.1830x; 3.1830x over previous
#include <cuda_runtime.h>
#include <cuda_fp16.h>
#include <math.h>
#include <stdint.h>

// ---------------- problem constants ----------------
static constexpr int BB=4096, D3=288, LZ=32, HH=512, OO=96, EE=8, GHD=128;
static constexpr int MBK = BB/128;   // 32 m-blocks (128-row blobs)

#define SWZ(o) ((o) ^ (((o) >> 3) & 0x70))

// ---------------- global scratch (pre-swizzled SW128 blobs; no allocs allowed) ----------------
// A blobs: [mblk128][kblk] tiles of 128 rows x 64 half cols = 8192 halves = 16KB
// W blobs: [e][nblk][kblk] tiles of 64 rows x 64 half cols = 4096 halves = 8KB
__device__ __align__(128) __half g_A0h[MBK*5*8192], g_A0l[MBK*5*8192];
__device__ __align__(128) __half g_A1h[MBK*9*8192], g_A1l[MBK*9*8192];
__device__ __align__(128) __half g_A2h[MBK*9*8192], g_A2l[MBK*9*8192];
__device__ __align__(128) __half g_A3h[MBK*8*8192], g_A3l[MBK*8*8192];
__device__ __align__(128) __half g_G1h[MBK*2*8192], g_G1l[MBK*2*8192];
__device__ __align__(128) __half g_W0h[8*8*5*4096], g_W0l[8*8*5*4096];
__device__ __align__(128) __half g_W1h[8*8*9*4096], g_W1l[8*8*9*4096];
__device__ __align__(128) __half g_W2h[8*8*9*4096], g_W2l[8*8*9*4096];
__device__ __align__(128) __half g_W3h[8*2*8*4096], g_W3l[8*2*8*4096];
__device__ __align__(128) __half g_gW1h[2*5*4096],  g_gW1l[2*5*4096];
__device__ __align__(128) __half g_gW2h[2*2*4096],  g_gW2l[2*2*4096];
__device__ float g_gh2[BB*GHD];
__device__ float g_gate[BB*EE];

// ---------------- PTX helpers ----------------
__device__ __forceinline__ uint32_t smem_u32(const void* p) {
    uint32_t a;
    asm("{ .reg .u64 t; cvta.to.shared.u64 t, %1; cvt.u32.u64 %0, t; }" : "=r"(a) : "l"(p));
    return a;
}
__device__ __forceinline__ void mbar_init(uint32_t m, uint32_t c) {
    asm volatile("mbarrier.init.shared.b64 [%0], %1;" :: "r"(m), "r"(c) : "memory");
}
__device__ __forceinline__ void mbar_expect(uint32_t m, uint32_t b) {
    asm volatile("mbarrier.arrive.expect_tx.shared.b64 _, [%0], %1;" :: "r"(m), "r"(b) : "memory");
}
__device__ __forceinline__ void mbar_arrive(uint32_t m) {
    asm volatile("mbarrier.arrive.shared.b64 _, [%0];" :: "r"(m) : "memory");
}
__device__ __forceinline__ void mbar_wait(uint32_t m, uint32_t ph) {
    uint32_t done;
    asm volatile("{\n\t.reg .pred p;\n\t"
        "mbarrier.try_wait.parity.acquire.cta.shared::cta.b64 p, [%1], %2;\n\t"
        "selp.b32 %0, 1, 0, p;\n\t}" : "=r"(done) : "r"(m), "r"(ph) : "memory");
    while (!done) {
        asm volatile("{\n\t.reg .pred p;\n\t"
            "mbarrier.try_wait.parity.acquire.cta.shared::cta.b64 p, [%1], %2, 0x989680;\n\t"
            "selp.b32 %0, 1, 0, p;\n\t}" : "=r"(done) : "r"(m), "r"(ph) : "memory");
    }
}
__device__ __forceinline__ void bulk_g2s(uint32_t dst, const void* src, uint32_t bytes, uint32_t mbar) {
    asm volatile("cp.async.bulk.shared::cluster.global.mbarrier::complete_tx::bytes [%0], [%1], %2, [%3];"
        :: "r"(dst), "l"(src), "r"(bytes), "r"(mbar) : "memory");
}
__device__ __forceinline__ void ldm_x4(uint32_t* r, uint32_t addr) {
    asm volatile("ldmatrix.sync.aligned.m8n8.x4.shared.b16 {%0,%1,%2,%3}, [%4];"
        : "=r"(r[0]), "=r"(r[1]), "=r"(r[2]), "=r"(r[3]) : "r"(addr));
}
__device__ __forceinline__ void mma16816(float* d, const uint32_t* a, uint32_t b0, uint32_t b1) {
    asm("mma.sync.aligned.m16n8k16.row.col.f32.f16.f16.f32 "
        "{%0,%1,%2,%3}, {%4,%5,%6,%7}, {%8,%9}, {%0,%1,%2,%3};"
        : "+f"(d[0]), "+f"(d[1]), "+f"(d[2]), "+f"(d[3])
        : "r"(a[0]), "r"(a[1]), "r"(a[2]), "r"(a[3]), "r"(b0), "r"(b1));
}
__device__ __forceinline__ float elu1(float x) { return x > 0.f ? x : expm1f(x); }

// ---------------- smem layout (MW2, 4-slot W ring; 2 CTAs/SM) ----------------
// BM=64: A stage = 8KB hi + 8KB lo; 2 stages = 32KB. W ring: 4 x 16KB = 64KB.
static constexpr int WS = 4;         // W ring slots
static constexpr int SMEM_MW2 = 32768 + WS*16384 + 2048 + 2048 + 256;  // 102656

// ---------------- blended expert GEMM (mma.sync HMMA, 3-term fp16 split, f32 acc) ----------------
// BM=64 (2 m-warps), BN=64 (2 n-warps), 1 producer warp -> 160 threads, 2 CTAs/SM.
template<int EXP, bool GATE, bool ACT, bool OUTF32>
__global__ void __launch_bounds__(160, 2) moe_gemm(
    const __half* __restrict__ Ah, const __half* __restrict__ Al, int kblks,
    const __half* __restrict__ Wh, const __half* __restrict__ Wl, int wnb,
    const float* __restrict__ bias, const float* __restrict__ gate, int ntot,
    __half* __restrict__ Oh, __half* __restrict__ Ol, int okb,
    float* __restrict__ C, int ldc)
{
    constexpr int MW = 2, CW = 4, NT = 160, BM = 64;
    constexpr int ABYTES = BM * 128;        // 8192
    constexpr int A_STG  = 2 * ABYTES;      // 16384
    constexpr int W_OFFc = 2 * A_STG;       // 32768
    constexpr int W_STRIDE = 16384;
    constexpr int GS_OFFc  = W_OFFc + WS * W_STRIDE;   // 98304
    constexpr int BS_OFFc  = GS_OFFc + 2048;
    constexpr int BAR_OFFc = BS_OFFc + 2048;

    extern __shared__ __align__(1024) uint8_t smem[];
    const uint32_t sb = smem_u32(smem);
    const int tid = threadIdx.x;
    const int lane = tid & 31, wid = tid >> 5;
    const int wm = wid % MW, wn = (wid / MW) & 1;
    const int mblk = blockIdx.y, nblk = blockIdx.x;

    const uint32_t bAf = sb + BAR_OFFc;          // 2 x 8B
    const uint32_t bAe = sb + BAR_OFFc + 16;     // 2 x 8B
    const uint32_t bWf = sb + BAR_OFFc + 32;     // 4 x 8B
    const uint32_t bWe = sb + BAR_OFFc + 64;     // 4 x 8B

    if (tid == 0) {
        for (int s = 0; s < 2; s++)  { mbar_init(bAf + s*8, 1); mbar_init(bAe + s*8, CW); }
        for (int s = 0; s < WS; s++) { mbar_init(bWf + s*8, 1); mbar_init(bWe + s*8, CW); }
    }
    float* gS = (float*)(smem + GS_OFFc);
    float* bS = (float*)(smem + BS_OFFc);
    if (GATE) {
        for (int i = tid; i < BM * EE; i += NT) gS[i] = gate[(size_t)mblk * BM * EE + i];
    }
    for (int i = tid; i < EXP * 64; i += NT) {
        int e = i >> 6, j = i & 63, o = nblk * 64 + j;
        bS[i] = (o < ntot) ? bias[e * ntot + o] : 0.f;
    }
    __syncthreads();

    if (wid == CW) {
        // ---------------- dedicated producer warp (lane 0 only) ----------------
        if (lane == 0) {
            for (int kb = 0; kb < kblks; kb++) {
                int as = kb & 1;
                if (kb >= 2) mbar_wait(bAe + as*8, ((kb >> 1) & 1) ^ 1);
                mbar_expect(bAf + as*8, 2 * ABYTES);
                // blobs hold 128 rows; BM=64 tile is the (mblk&1) half (row-major within blob)
                size_t aoff = ((size_t)(mblk >> 1) * kblks + kb) * 8192 + (size_t)(mblk & 1) * 4096;
                bulk_g2s(sb + as*A_STG,          Ah + aoff, ABYTES, bAf + as*8);
                bulk_g2s(sb + as*A_STG + ABYTES, Al + aoff, ABYTES, bAf + as*8);
                for (int e = 0; e < EXP; e++) {
                    int wu = kb * EXP + e, s = wu & (WS - 1);
                    if (wu >= WS) mbar_wait(bWe + s*8, ((wu / WS) & 1) ^ 1);
                    mbar_expect(bWf + s*8, 16384);
                    size_t woff = (((size_t)e * wnb + nblk) * kblks + kb) * 4096;
                    bulk_g2s(sb + W_OFFc + s*W_STRIDE,        Wh + woff, 8192, bWf + s*8);
                    bulk_g2s(sb + W_OFFc + s*W_STRIDE + 8192, Wl + woff, 8192, bWf + s*8);
                }
            }
        }
        return;
    }

    // ---------------- compute warps (0-3) ----------------
    uint32_t offA[2][4], offB[2][4];
#pragma unroll
    for (int i = 0; i < 2; i++)
#pragma unroll
        for (int j = 0; j < 4; j++)
            offA[i][j] = SWZ((uint32_t)((wm*32 + i*16 + (lane & 15)) * 128 + j*32 + (lane >> 4) * 16));
#pragma unroll
    for (int p = 0; p < 2; p++)
#pragma unroll
        for (int j = 0; j < 4; j++)
            offB[p][j] = SWZ((uint32_t)((wn*32 + p*16 + (lane & 15)) * 128 + j*32 + (lane >> 4) * 16));

    float acc[2][4][4];
#pragma unroll
    for (int i = 0; i < 2; i++)
#pragma unroll
        for (int n8 = 0; n8 < 4; n8++)
#pragma unroll
            for (int q = 0; q < 4; q++) acc[i][n8][q] = 0.f;

    int wu = 0;
#pragma unroll 1
    for (int kb = 0; kb < kblks; kb++) {
        int as = kb & 1;
        mbar_wait(bAf + as*8, (kb >> 1) & 1);
        const uint32_t Ab = sb + as*A_STG;
        uint32_t aH[2][4][4], aL[2][4][4];   // A fragments resident across expert loop
#pragma unroll
        for (int i = 0; i < 2; i++)
#pragma unroll
            for (int j = 0; j < 4; j++) {
                ldm_x4(aH[i][j], Ab + offA[i][j]);
                ldm_x4(aL[i][j], Ab + ABYTES + offA[i][j]);
            }
        if (lane == 0) mbar_arrive(bAe + as*8);
#pragma unroll 1
        for (int e = 0; e < EXP; e++) {
            int s = wu & (WS - 1);
            mbar_wait(bWf + s*8, (wu / WS) & 1);
            const uint32_t Wb = sb + W_OFFc + s*W_STRIDE;
            if (GATE) {
                float part[2][4][4];
#pragma unroll
                for (int i = 0; i < 2; i++)
#pragma unroll
                    for (int n8 = 0; n8 < 4; n8++)
#pragma unroll
                        for (int q = 0; q < 4; q++) part[i][n8][q] = 0.f;
#pragma unroll
                for (int j = 0; j < 4; j++) {
                    uint32_t b0h[4], b1h[4], b0l[4], b1l[4];
                    ldm_x4(b0h, Wb + offB[0][j]);
                    ldm_x4(b1h, Wb + offB[1][j]);
                    ldm_x4(b0l, Wb + 8192 + offB[0][j]);
                    ldm_x4(b1l, Wb + 8192 + offB[1][j]);
#pragma unroll
                    for (int i = 0; i < 2; i++)
#pragma unroll
                        for (int n8 = 0; n8 < 4; n8++) {
                            const uint32_t* bh = (n8 < 2) ? b0h : b1h;
                            const uint32_t* bl = (n8 < 2) ? b0l : b1l;
                            int q = n8 & 1;
                            mma16816(part[i][n8], aH[i][j], bh[q], bh[2 + q]);
                            mma16816(part[i][n8], aL[i][j], bh[q], bh[2 + q]);
                            mma16816(part[i][n8], aH[i][j], bl[q], bl[2 + q]);
                        }
                }
                if (lane == 0) mbar_arrive(bWe + s*8);
                int r0 = wm*32 + (lane >> 2);
                float g0 = gS[(r0 + 0)  * EE + e], g1 = gS[(r0 + 8)  * EE + e];
                float g2 = gS[(r0 + 16) * EE + e], g3 = gS[(r0 + 24) * EE + e];
#pragma unroll
                for (int n8 = 0; n8 < 4; n8++) {
                    acc[0][n8][0] += g0 * part[0][n8][0];
                    acc[0][n8][1] += g0 * part[0][n8][1];
                    acc[0][n8][2] += g1 * part[0][n8][2];
                    acc[0][n8][3] += g1 * part[0][n8][3];
                    acc[1][n8][0] += g2 * part[1][n8][0];
                    acc[1][n8][1] += g2 * part[1][n8][1];
                    acc[1][n8][2] += g3 * part[1][n8][2];
                    acc[1][n8][3] += g3 * part[1][n8][3];
                }
            } else {
#pragma unroll
                for (int j = 0; j < 4; j++) {
                    uint32_t b0h[4], b1h[4], b0l[4], b1l[4];
                    ldm_x4(b0h, Wb + offB[0][j]);
                    ldm_x4(b1h, Wb + offB[1][j]);
                    ldm_x4(b0l, Wb + 8192 + offB[0][j]);
                    ldm_x4(b1l, Wb + 8192 + offB[1][j]);
#pragma unroll
                    for (int i = 0; i < 2; i++)
#pragma unroll
                        for (int n8 = 0; n8 < 4; n8++) {
                            const uint32_t* bh = (n8 < 2) ? b0h : b1h;
                            const uint32_t* bl = (n8 < 2) ? b0l : b1l;
                            int q = n8 & 1;
                            mma16816(acc[i][n8], aH[i][j], bh[q], bh[2 + q]);
                            mma16816(acc[i][n8], aL[i][j], bh[q], bh[2 + q]);
                            mma16816(acc[i][n8], aH[i][j], bl[q], bl[2 + q]);
                        }
                }
                if (lane == 0) mbar_arrive(bWe + s*8);
            }
            wu++;
        }
    }

    // ---- epilogue: blended bias + activation + store ----
    const int rbase = wm*32 + (lane >> 2);
    const int cbase = wn*32 + (lane & 3) * 2;
#pragma unroll
    for (int i = 0; i < 2; i++) {
#pragma unroll
        for (int hf = 0; hf < 2; hf++) {
            int lr = rbase + i*16 + hf*8;
            int gr = mblk*BM + lr;
#pragma unroll
            for (int n8 = 0; n8 < 4; n8++) {
                int cl = cbase + n8*8;
                float v0 = acc[i][n8][hf*2 + 0];
                float v1 = acc[i][n8][hf*2 + 1];
                if (GATE) {
                    float s0 = 0.f, s1 = 0.f;
#pragma unroll
                    for (int e = 0; e < EXP; e++) {
                        float g = gS[lr * EE + e];
                        s0 += g * bS[e*64 + cl];
                        s1 += g * bS[e*64 + cl + 1];
                    }
                    v0 += s0; v1 += s1;
                } else { v0 += bS[cl]; v1 += bS[cl + 1]; }
                if (ACT) { v0 = elu1(v0); v1 = elu1(v1); }
                if (OUTF32) {
                    int c = nblk*64 + cl;
                    if (c < ntot)     C[(size_t)gr * ldc + c]     = v0;
                    if (c + 1 < ntot) C[(size_t)gr * ldc + c + 1] = v1;
                } else {
                    __half h0 = __float2half_rn(v0), h1 = __float2half_rn(v1);
                    __half l0 = __float2half_rn(v0 - __half2float(h0));
                    __half l1 = __float2half_rn(v1 - __half2float(h1));
                    int gcol = nblk*64 + cl;
                    uint32_t off = SWZ((uint32_t)((gr & 127) * 128 + (gcol & 63) * 2));
                    size_t bidx = ((size_t)(gr >> 7) * okb + (gcol >> 6)) * 8192;
                    *(__half2*)((uint8_t*)(Oh + bidx) + off) = __halves2half2(h0, h1);
                    *(__half2*)((uint8_t*)(Ol + bidx) + off) = __halves2half2(l0, l1);
                }
            }
        }
    }
}

// ---------------- prepack: fp32 -> fp16 hi/lo split, SW128-swizzled blobs ----------------
__device__ __forceinline__ void split_store(uint8_t* bh, uint8_t* bl, uint32_t sw, float4 v) {
    float vv[4] = {v.x, v.y, v.z, v.w};
    uint32_t h[4], l[4];
#pragma unroll
    for (int q = 0; q < 4; q++) {
        __half hh = __float2half_rn(vv[q]);
        __half ll = __float2half_rn(vv[q] - __half2float(hh));
        h[q] = (uint32_t)__half_as_ushort(hh);
        l[q] = (uint32_t)__half_as_ushort(ll);
    }
    *(uint2*)(bh + sw) = make_uint2(h[0] | (h[1] << 16), h[2] | (h[3] << 16));
    *(uint2*)(bl + sw) = make_uint2(l[0] | (l[1] << 16), l[2] | (l[3] << 16));
}

struct PWJob { const float* W; __half* Dh; __half* Dl; int N, K, nblks, kblks, blk0, cnt; };
struct PWJobs { PWJob j[6]; };

__global__ void prepack_w_all(PWJobs jobs) {
    int b = blockIdx.x;
#pragma unroll 1
    for (int ji = 0; ji < 6; ji++) {
        const PWJob& J = jobs.j[ji];
        if (b < J.blk0 || b >= J.blk0 + J.cnt) continue;
        int t = b - J.blk0;
        int kb = t % J.kblks, nb = (t / J.kblks) % J.nblks, e = t / (J.kblks * J.nblks);
        const float* src = J.W + (size_t)e * J.N * J.K;
        uint8_t* bh = (uint8_t*)(J.Dh + (size_t)t * 4096);
        uint8_t* bl = (uint8_t*)(J.Dl + (size_t)t * 4096);
        for (int i = threadIdx.x; i < 1024; i += 256) {
            int r = i >> 4, c4 = i & 15;
            int n = nb * 64 + r, k = kb * 64 + c4 * 4;
            float4 v = make_float4(0.f, 0.f, 0.f, 0.f);
            if (n < J.N && k < J.K) v = *(const float4*)(src + (size_t)n * J.K + k);
            split_store(bh, bl, SWZ((uint32_t)(r * 128 + c4 * 8)), v);
        }
        return;
    }
}

__global__ void prepack_a_all(const float* __restrict__ x, const float* __restrict__ z) {
    int b = blockIdx.x;
    if (b < MBK * 5) {
        int kb = b % 5, mb = b / 5;
        uint8_t* bh = (uint8_t*)(g_A0h + (size_t)b * 8192);
        uint8_t* bl = (uint8_t*)(g_A0l + (size_t)b * 8192);
        for (int i = threadIdx.x; i < 2048; i += 256) {
            int r = i >> 4, c4 = i & 15;
            int row = mb * 128 + r, k = kb * 64 + c4 * 4;
            float4 v;
            if (k < D3) v = *(const float4*)(x + (size_t)row * D3 + k);
            else        v = *(const float4*)(z + (size_t)row * LZ + (k - D3));
            split_store(bh, bl, SWZ((uint32_t)(r * 128 + c4 * 8)), v);
        }
    } else {
        int mb = b - MBK * 5;
        size_t off = ((size_t)mb * 9 + 8) * 8192;
        for (int i = threadIdx.x; i < 2048; i += 256) {
            int r = i >> 4, c4 = i & 15;
            int row = mb * 128 + r, k = c4 * 4;
            float4 v = make_float4(0.f, 0.f, 0.f, 0.f);
            if (k < LZ) v = *(const float4*)(z + (size_t)row * LZ + k);
            uint32_t sw = SWZ((uint32_t)(r * 128 + c4 * 8));
            split_store((uint8_t*)(g_A1h + off), (uint8_t*)(g_A1l + off), sw, v);
            split_store((uint8_t*)(g_A2h + off), (uint8_t*)(g_A2l + off), sw, v);
        }
    }
}

// ---------------- gating logits + softmax (warp-per-row, smem-staged gW3) ----------------
__global__ void logits_softmax(const float* __restrict__ h2,
                               const float* __restrict__ gW3,
                               const float* __restrict__ gb3) {
    __shared__ float ws[8][128];
    __shared__ float bsm[8];
    int tid = threadIdx.x, lane = tid & 31, w = tid >> 5;
    for (int i = tid; i < 8 * 128; i += 256) ws[i >> 7][i & 127] = gW3[i];
    if (tid < 8) bsm[tid] = gb3[tid];
    __syncthreads();
    int row = blockIdx.x * 8 + w;
    float4 v = ((const float4*)(h2 + (size_t)row * GHD))[lane];
    float p[8];
#pragma unroll
    for (int e = 0; e < 8; e++) {
        float4 wv = ((const float4*)ws[e])[lane];
        p[e] = v.x*wv.x + v.y*wv.y + v.z*wv.z + v.w*wv.w;
    }
#pragma unroll
    for (int o = 16; o; o >>= 1)
#pragma unroll
        for (int e = 0; e < 8; e++) p[e] += __shfl_xor_sync(0xffffffffu, p[e], o);
    if (lane < 8) {
        float m = -1e30f;
#pragma unroll
        for (int e = 0; e < 8; e++) { p[e] += bsm[e]; m = fmaxf(m, p[e]); }
        float Z = 0.f;
#pragma unroll
        for (int e = 0; e < 8; e++) Z += expf(p[e] - m);
        float myp = p[0];
#pragma unroll
        for (int e = 1; e < 8; e++) myp = (lane == e) ? p[e] : myp;
        g_gate[row * 8 + lane] = expf(myp - m) / Z;
    }
}

// ---------------- host ----------------
extern "C" void kernel_launch(void* const* d_in, const int* in_sizes, int n_in,
                              void* d_out, int out_size) {
    const float* x   = (const float*)d_in[0];
    const float* z   = (const float*)d_in[1];
    const float* W0  = (const float*)d_in[2];
    const float* b0  = (const float*)d_in[3];
    const float* W1  = (const float*)d_in[4];
    const float* b1  = (const float*)d_in[5];
    const float* W2  = (const float*)d_in[6];
    const float* b2  = (const float*)d_in[7];
    const float* W3  = (const float*)d_in[8];
    const float* b3  = (const float*)d_in[9];
    const float* gW1 = (const float*)d_in[10];
    const float* gb1 = (const float*)d_in[11];
    const float* gW2 = (const float*)d_in[12];
    const float* gb2 = (const float*)d_in[13];
    const float* gW3 = (const float*)d_in[14];
    const float* gb3 = (const float*)d_in[15];
    float* out = (float*)d_out;
    (void)in_sizes; (void)n_in; (void)out_size;

    __half *A0h,*A0l,*A1h,*A1l,*A2h,*A2l,*A3h,*A3l,*G1h,*G1l;
    __half *pW0h,*pW0l,*pW1h,*pW1l,*pW2h,*pW2l,*pW3h,*pW3l,*pg1h,*pg1l,*pg2h,*pg2l;
    float *gh2, *gate;
    cudaGetSymbolAddress((void**)&A0h, g_A0h); cudaGetSymbolAddress((void**)&A0l, g_A0l);
    cudaGetSymbolAddress((void**)&A1h, g_A1h); cudaGetSymbolAddress((void**)&A1l, g_A1l);
    cudaGetSymbolAddress((void**)&A2h, g_A2h); cudaGetSymbolAddress((void**)&A2l, g_A2l);
    cudaGetSymbolAddress((void**)&A3h, g_A3h); cudaGetSymbolAddress((void**)&A3l, g_A3l);
    cudaGetSymbolAddress((void**)&G1h, g_G1h); cudaGetSymbolAddress((void**)&G1l, g_G1l);
    cudaGetSymbolAddress((void**)&pW0h, g_W0h); cudaGetSymbolAddress((void**)&pW0l, g_W0l);
    cudaGetSymbolAddress((void**)&pW1h, g_W1h); cudaGetSymbolAddress((void**)&pW1l, g_W1l);
    cudaGetSymbolAddress((void**)&pW2h, g_W2h); cudaGetSymbolAddress((void**)&pW2l, g_W2l);
    cudaGetSymbolAddress((void**)&pW3h, g_W3h); cudaGetSymbolAddress((void**)&pW3l, g_W3l);
    cudaGetSymbolAddress((void**)&pg1h, g_gW1h); cudaGetSymbolAddress((void**)&pg1l, g_gW1l);
    cudaGetSymbolAddress((void**)&pg2h, g_gW2h); cudaGetSymbolAddress((void**)&pg2l, g_gW2l);
    cudaGetSymbolAddress((void**)&gh2, g_gh2); cudaGetSymbolAddress((void**)&gate, g_gate);

    cudaFuncSetAttribute(moe_gemm<1,false,true,false>, cudaFuncAttributeMaxDynamicSharedMemorySize, SMEM_MW2);
    cudaFuncSetAttribute(moe_gemm<1,false,true,true>,  cudaFuncAttributeMaxDynamicSharedMemorySize, SMEM_MW2);
    cudaFuncSetAttribute(moe_gemm<8,true,true,false>,  cudaFuncAttributeMaxDynamicSharedMemorySize, SMEM_MW2);
    cudaFuncSetAttribute(moe_gemm<8,true,false,true>,  cudaFuncAttributeMaxDynamicSharedMemorySize, SMEM_MW2);

    // prepack weights (one launch) + inputs (one launch)
    PWJobs jobs;
    jobs.j[0] = {W0,  pW0h, pW0l, HH,  320, 8, 5, 0,    320};
    jobs.j[1] = {W1,  pW1h, pW1l, HH,  544, 8, 9, 320,  576};
    jobs.j[2] = {W2,  pW2h, pW2l, HH,  544, 8, 9, 896,  576};
    jobs.j[3] = {W3,  pW3h, pW3l, OO,  512, 2, 8, 1472, 128};
    jobs.j[4] = {gW1, pg1h, pg1l, GHD, 320, 2, 5, 1600, 10};
    jobs.j[5] = {gW2, pg2h, pg2l, GHD, GHD, 2, 2, 1610, 4};
    prepack_w_all<<<1614, 256>>>(jobs);
    prepack_a_all<<<MBK*5 + MBK, 256>>>(x, z);

    // gating MLP (M64 tiles -> 128 CTAs each)
    moe_gemm<1,false,true,false><<<dim3(2, 64), 160, SMEM_MW2>>>(
        A0h, A0l, 5, pg1h, pg1l, 2, gb1, nullptr, GHD, G1h, G1l, 2, nullptr, 0);
    moe_gemm<1,false,true,true><<<dim3(2, 64), 160, SMEM_MW2>>>(
        G1h, G1l, 2, pg2h, pg2l, 2, gb2, nullptr, GHD, nullptr, nullptr, 0, gh2, GHD);
    logits_softmax<<<BB/8, 256>>>(gh2, gW3, gb3);

    // blended expert layers (BM=64 tiles, 512/512/512/128 CTAs, 2 CTAs/SM)
    moe_gemm<8,true,true,false><<<dim3(8, 64), 160, SMEM_MW2>>>(
        A0h, A0l, 5, pW0h, pW0l, 8, b0, gate, HH, A1h, A1l, 9, nullptr, 0);
    moe_gemm<8,true,true,false><<<dim3(8, 64), 160, SMEM_MW2>>>(
        A1h, A1l, 9, pW1h, pW1l, 8, b1, gate, HH, A2h, A2l, 9, nullptr, 0);
    moe_gemm<8,true,true,false><<<dim3(8, 64), 160, SMEM_MW2>>>(
        A2h, A2l, 9, pW2h, pW2l, 8, b2, gate, HH, A3h, A3l, 8, nullptr, 0);
    moe_gemm<8,true,false,true><<<dim3(2, 64), 160, SMEM_MW2>>>(
        A3h, A3l, 8, pW3h, pW3l, 2, b3, gate, OO, nullptr, nullptr, 0, out, OO);
}

// round 14
// speedup vs baseline: 3.9747x; 1.2487x over previous
#include <cuda_runtime.h>
#include <cuda_fp16.h>
#include <math.h>
#include <stdint.h>

// ---------------- problem constants ----------------
static constexpr int BB=4096, D3=288, LZ=32, HH=512, OO=96, EE=8, GHD=128;
static constexpr int MBK = BB/128;   // 32 m-blocks (128-row blobs)

#define SWZ(o) ((o) ^ (((o) >> 3) & 0x70))

// ---------------- global scratch (pre-swizzled SW128 blobs; no allocs allowed) ----------------
// A blobs: [mblk128][kblk] tiles of 128 rows x 64 half cols = 8192 halves = 16KB
// W blobs: [e][nblk][kblk] tiles of 64 rows x 64 half cols = 4096 halves = 8KB
__device__ __align__(128) __half g_A0h[MBK*5*8192], g_A0l[MBK*5*8192];
__device__ __align__(128) __half g_A1h[MBK*9*8192], g_A1l[MBK*9*8192];
__device__ __align__(128) __half g_A2h[MBK*9*8192], g_A2l[MBK*9*8192];
__device__ __align__(128) __half g_A3h[MBK*8*8192], g_A3l[MBK*8*8192];
__device__ __align__(128) __half g_G1h[MBK*2*8192], g_G1l[MBK*2*8192];
__device__ __align__(128) __half g_W0h[8*8*5*4096], g_W0l[8*8*5*4096];
__device__ __align__(128) __half g_W1h[8*8*9*4096], g_W1l[8*8*9*4096];
__device__ __align__(128) __half g_W2h[8*8*9*4096], g_W2l[8*8*9*4096];
__device__ __align__(128) __half g_W3h[8*2*8*4096], g_W3l[8*2*8*4096];
__device__ __align__(128) __half g_gW1h[2*5*4096],  g_gW1l[2*5*4096];
__device__ __align__(128) __half g_gW2h[2*2*4096],  g_gW2l[2*2*4096];
__device__ float g_gh2[BB*GHD];
__device__ float g_gate[BB*EE];

// ---------------- PTX helpers ----------------
__device__ __forceinline__ uint32_t smem_u32(const void* p) {
    uint32_t a;
    asm("{ .reg .u64 t; cvta.to.shared.u64 t, %1; cvt.u32.u64 %0, t; }" : "=r"(a) : "l"(p));
    return a;
}
__device__ __forceinline__ void mbar_init(uint32_t m, uint32_t c) {
    asm volatile("mbarrier.init.shared.b64 [%0], %1;" :: "r"(m), "r"(c) : "memory");
}
__device__ __forceinline__ void mbar_expect(uint32_t m, uint32_t b) {
    asm volatile("mbarrier.arrive.expect_tx.shared.b64 _, [%0], %1;" :: "r"(m), "r"(b) : "memory");
}
__device__ __forceinline__ void mbar_arrive(uint32_t m) {
    asm volatile("mbarrier.arrive.shared.b64 _, [%0];" :: "r"(m) : "memory");
}
__device__ __forceinline__ void mbar_wait(uint32_t m, uint32_t ph) {
    uint32_t done;
    asm volatile("{\n\t.reg .pred p;\n\t"
        "mbarrier.try_wait.parity.acquire.cta.shared::cta.b64 p, [%1], %2;\n\t"
        "selp.b32 %0, 1, 0, p;\n\t}" : "=r"(done) : "r"(m), "r"(ph) : "memory");
    while (!done) {
        asm volatile("{\n\t.reg .pred p;\n\t"
            "mbarrier.try_wait.parity.acquire.cta.shared::cta.b64 p, [%1], %2, 0x989680;\n\t"
            "selp.b32 %0, 1, 0, p;\n\t}" : "=r"(done) : "r"(m), "r"(ph) : "memory");
    }
}
__device__ __forceinline__ void bulk_g2s(uint32_t dst, const void* src, uint32_t bytes, uint32_t mbar) {
    asm volatile("cp.async.bulk.shared::cluster.global.mbarrier::complete_tx::bytes [%0], [%1], %2, [%3];"
        :: "r"(dst), "l"(src), "r"(bytes), "r"(mbar) : "memory");
}
__device__ __forceinline__ void ldm_x4(uint32_t* r, uint32_t addr) {
    asm volatile("ldmatrix.sync.aligned.m8n8.x4.shared.b16 {%0,%1,%2,%3}, [%4];"
        : "=r"(r[0]), "=r"(r[1]), "=r"(r[2]), "=r"(r[3]) : "r"(addr));
}
__device__ __forceinline__ void mma16816(float* d, const uint32_t* a, uint32_t b0, uint32_t b1) {
    asm("mma.sync.aligned.m16n8k16.row.col.f32.f16.f16.f32 "
        "{%0,%1,%2,%3}, {%4,%5,%6,%7}, {%8,%9}, {%0,%1,%2,%3};"
        : "+f"(d[0]), "+f"(d[1]), "+f"(d[2]), "+f"(d[3])
        : "r"(a[0]), "r"(a[1]), "r"(a[2]), "r"(a[3]), "r"(b0), "r"(b1));
}
__device__ __forceinline__ float elu1(float x) { return x > 0.f ? x : expm1f(x); }

// ---------------- blended expert GEMM (mma.sync HMMA, fp16 split, f32 acc) ----------------
// BM=64 (2 m-warps), BN=64 (2 n-warps), 1 producer warp -> 160 threads, 2 CTAs/SM.
// WLO=true : 3 terms (Ah*Wh + Al*Wh + Ah*Wl), W slots 16KB (hi+lo).
// WLO=false: 2 terms (Ah*Wh + Al*Wh),          W slots  8KB (hi only).
template<int EXP, bool GATE, bool ACT, bool OUTF32, bool WLO>
__global__ void __launch_bounds__(160, 2) moe_gemm(
    const __half* __restrict__ Ah, const __half* __restrict__ Al, int kblks,
    const __half* __restrict__ Wh, const __half* __restrict__ Wl, int wnb,
    const float* __restrict__ bias, const float* __restrict__ gate, int ntot,
    __half* __restrict__ Oh, __half* __restrict__ Ol, int okb,
    float* __restrict__ C, int ldc)
{
    constexpr int MW = 2, CW = 4, NT = 160, BM = 64, WS = 4;
    constexpr int ABYTES = BM * 128;        // 8192
    constexpr int A_STG  = 2 * ABYTES;      // 16384 (A hi+lo always)
    constexpr int W_OFFc = 2 * A_STG;       // 32768
    constexpr int W_STRIDE = WLO ? 16384 : 8192;
    constexpr int GS_OFFc  = W_OFFc + WS * W_STRIDE;
    constexpr int BS_OFFc  = GS_OFFc + 2048;
    constexpr int BAR_OFFc = BS_OFFc + 2048;

    extern __shared__ __align__(1024) uint8_t smem[];
    const uint32_t sb = smem_u32(smem);
    const int tid = threadIdx.x;
    const int lane = tid & 31, wid = tid >> 5;
    const int wm = wid % MW, wn = (wid / MW) & 1;
    const int mblk = blockIdx.y, nblk = blockIdx.x;

    const uint32_t bAf = sb + BAR_OFFc;          // 2 x 8B
    const uint32_t bAe = sb + BAR_OFFc + 16;     // 2 x 8B
    const uint32_t bWf = sb + BAR_OFFc + 32;     // 4 x 8B
    const uint32_t bWe = sb + BAR_OFFc + 64;     // 4 x 8B

    if (tid == 0) {
        for (int s = 0; s < 2; s++)  { mbar_init(bAf + s*8, 1); mbar_init(bAe + s*8, CW); }
        for (int s = 0; s < WS; s++) { mbar_init(bWf + s*8, 1); mbar_init(bWe + s*8, CW); }
    }
    float* gS = (float*)(smem + GS_OFFc);
    float* bS = (float*)(smem + BS_OFFc);
    if (GATE) {
        for (int i = tid; i < BM * EE; i += NT) gS[i] = gate[(size_t)mblk * BM * EE + i];
    }
    for (int i = tid; i < EXP * 64; i += NT) {
        int e = i >> 6, j = i & 63, o = nblk * 64 + j;
        bS[i] = (o < ntot) ? bias[e * ntot + o] : 0.f;
    }
    __syncthreads();

    if (wid == CW) {
        // ---------------- dedicated producer warp (lane 0 only) ----------------
        if (lane == 0) {
            for (int kb = 0; kb < kblks; kb++) {
                int as = kb & 1;
                if (kb >= 2) mbar_wait(bAe + as*8, ((kb >> 1) & 1) ^ 1);
                mbar_expect(bAf + as*8, 2 * ABYTES);
                // blobs hold 128 rows; BM=64 tile is the (mblk&1) half
                size_t aoff = ((size_t)(mblk >> 1) * kblks + kb) * 8192 + (size_t)(mblk & 1) * 4096;
                bulk_g2s(sb + as*A_STG,          Ah + aoff, ABYTES, bAf + as*8);
                bulk_g2s(sb + as*A_STG + ABYTES, Al + aoff, ABYTES, bAf + as*8);
                for (int e = 0; e < EXP; e++) {
                    int wu = kb * EXP + e, s = wu & (WS - 1);
                    if (wu >= WS) mbar_wait(bWe + s*8, ((wu / WS) & 1) ^ 1);
                    mbar_expect(bWf + s*8, WLO ? 16384 : 8192);
                    size_t woff = (((size_t)e * wnb + nblk) * kblks + kb) * 4096;
                    bulk_g2s(sb + W_OFFc + s*W_STRIDE, Wh + woff, 8192, bWf + s*8);
                    if (WLO)
                        bulk_g2s(sb + W_OFFc + s*W_STRIDE + 8192, Wl + woff, 8192, bWf + s*8);
                }
            }
        }
        return;
    }

    // ---------------- compute warps (0-3) ----------------
    uint32_t offA[2][4], offB[2][4];
#pragma unroll
    for (int i = 0; i < 2; i++)
#pragma unroll
        for (int j = 0; j < 4; j++)
            offA[i][j] = SWZ((uint32_t)((wm*32 + i*16 + (lane & 15)) * 128 + j*32 + (lane >> 4) * 16));
#pragma unroll
    for (int p = 0; p < 2; p++)
#pragma unroll
        for (int j = 0; j < 4; j++)
            offB[p][j] = SWZ((uint32_t)((wn*32 + p*16 + (lane & 15)) * 128 + j*32 + (lane >> 4) * 16));

    float acc[2][4][4];
#pragma unroll
    for (int i = 0; i < 2; i++)
#pragma unroll
        for (int n8 = 0; n8 < 4; n8++)
#pragma unroll
            for (int q = 0; q < 4; q++) acc[i][n8][q] = 0.f;

    int wu = 0;
#pragma unroll 1
    for (int kb = 0; kb < kblks; kb++) {
        int as = kb & 1;
        mbar_wait(bAf + as*8, (kb >> 1) & 1);
        const uint32_t Ab = sb + as*A_STG;
        uint32_t aH[2][4][4], aL[2][4][4];   // A fragments resident across expert loop
#pragma unroll
        for (int i = 0; i < 2; i++)
#pragma unroll
            for (int j = 0; j < 4; j++) {
                ldm_x4(aH[i][j], Ab + offA[i][j]);
                ldm_x4(aL[i][j], Ab + ABYTES + offA[i][j]);
            }
        if (lane == 0) mbar_arrive(bAe + as*8);
#pragma unroll 1
        for (int e = 0; e < EXP; e++) {
            int s = wu & (WS - 1);
            mbar_wait(bWf + s*8, (wu / WS) & 1);
            const uint32_t Wb = sb + W_OFFc + s*W_STRIDE;
            if (GATE) {
                float part[2][4][4];
#pragma unroll
                for (int i = 0; i < 2; i++)
#pragma unroll
                    for (int n8 = 0; n8 < 4; n8++)
#pragma unroll
                        for (int q = 0; q < 4; q++) part[i][n8][q] = 0.f;
#pragma unroll
                for (int j = 0; j < 4; j++) {
                    uint32_t b0h[4], b1h[4], b0l[4], b1l[4];
                    ldm_x4(b0h, Wb + offB[0][j]);
                    ldm_x4(b1h, Wb + offB[1][j]);
                    if (WLO) {
                        ldm_x4(b0l, Wb + 8192 + offB[0][j]);
                        ldm_x4(b1l, Wb + 8192 + offB[1][j]);
                    }
#pragma unroll
                    for (int i = 0; i < 2; i++)
#pragma unroll
                        for (int n8 = 0; n8 < 4; n8++) {
                            const uint32_t* bh = (n8 < 2) ? b0h : b1h;
                            int q = n8 & 1;
                            mma16816(part[i][n8], aH[i][j], bh[q], bh[2 + q]);
                            mma16816(part[i][n8], aL[i][j], bh[q], bh[2 + q]);
                            if (WLO) {
                                const uint32_t* bl = (n8 < 2) ? b0l : b1l;
                                mma16816(part[i][n8], aH[i][j], bl[q], bl[2 + q]);
                            }
                        }
                }
                if (lane == 0) mbar_arrive(bWe + s*8);
                int r0 = wm*32 + (lane >> 2);
                float g0 = gS[(r0 + 0)  * EE + e], g1 = gS[(r0 + 8)  * EE + e];
                float g2 = gS[(r0 + 16) * EE + e], g3 = gS[(r0 + 24) * EE + e];
#pragma unroll
                for (int n8 = 0; n8 < 4; n8++) {
                    acc[0][n8][0] += g0 * part[0][n8][0];
                    acc[0][n8][1] += g0 * part[0][n8][1];
                    acc[0][n8][2] += g1 * part[0][n8][2];
                    acc[0][n8][3] += g1 * part[0][n8][3];
                    acc[1][n8][0] += g2 * part[1][n8][0];
                    acc[1][n8][1] += g2 * part[1][n8][1];
                    acc[1][n8][2] += g3 * part[1][n8][2];
                    acc[1][n8][3] += g3 * part[1][n8][3];
                }
            } else {
#pragma unroll
                for (int j = 0; j < 4; j++) {
                    uint32_t b0h[4], b1h[4], b0l[4], b1l[4];
                    ldm_x4(b0h, Wb + offB[0][j]);
                    ldm_x4(b1h, Wb + offB[1][j]);
                    if (WLO) {
                        ldm_x4(b0l, Wb + 8192 + offB[0][j]);
                        ldm_x4(b1l, Wb + 8192 + offB[1][j]);
                    }
#pragma unroll
                    for (int i = 0; i < 2; i++)
#pragma unroll
                        for (int n8 = 0; n8 < 4; n8++) {
                            const uint32_t* bh = (n8 < 2) ? b0h : b1h;
                            int q = n8 & 1;
                            mma16816(acc[i][n8], aH[i][j], bh[q], bh[2 + q]);
                            mma16816(acc[i][n8], aL[i][j], bh[q], bh[2 + q]);
                            if (WLO) {
                                const uint32_t* bl = (n8 < 2) ? b0l : b1l;
                                mma16816(acc[i][n8], aH[i][j], bl[q], bl[2 + q]);
                            }
                        }
                }
                if (lane == 0) mbar_arrive(bWe + s*8);
            }
            wu++;
        }
    }

    // ---- epilogue: blended bias + activation + store ----
    const int rbase = wm*32 + (lane >> 2);
    const int cbase = wn*32 + (lane & 3) * 2;
#pragma unroll
    for (int i = 0; i < 2; i++) {
#pragma unroll
        for (int hf = 0; hf < 2; hf++) {
            int lr = rbase + i*16 + hf*8;
            int gr = mblk*BM + lr;
#pragma unroll
            for (int n8 = 0; n8 < 4; n8++) {
                int cl = cbase + n8*8;
                float v0 = acc[i][n8][hf*2 + 0];
                float v1 = acc[i][n8][hf*2 + 1];
                if (GATE) {
                    float s0 = 0.f, s1 = 0.f;
#pragma unroll
                    for (int e = 0; e < EXP; e++) {
                        float g = gS[lr * EE + e];
                        s0 += g * bS[e*64 + cl];
                        s1 += g * bS[e*64 + cl + 1];
                    }
                    v0 += s0; v1 += s1;
                } else { v0 += bS[cl]; v1 += bS[cl + 1]; }
                if (ACT) { v0 = elu1(v0); v1 = elu1(v1); }
                if (OUTF32) {
                    int c = nblk*64 + cl;
                    if (c < ntot)     C[(size_t)gr * ldc + c]     = v0;
                    if (c + 1 < ntot) C[(size_t)gr * ldc + c + 1] = v1;
                } else {
                    __half h0 = __float2half_rn(v0), h1 = __float2half_rn(v1);
                    __half l0 = __float2half_rn(v0 - __half2float(h0));
                    __half l1 = __float2half_rn(v1 - __half2float(h1));
                    int gcol = nblk*64 + cl;
                    uint32_t off = SWZ((uint32_t)((gr & 127) * 128 + (gcol & 63) * 2));
                    size_t bidx = ((size_t)(gr >> 7) * okb + (gcol >> 6)) * 8192;
                    *(__half2*)((uint8_t*)(Oh + bidx) + off) = __halves2half2(h0, h1);
                    *(__half2*)((uint8_t*)(Ol + bidx) + off) = __halves2half2(l0, l1);
                }
            }
        }
    }
}

// ---------------- prepack: fp32 -> fp16 hi/lo split, SW128-swizzled blobs ----------------
__device__ __forceinline__ void split_store(uint8_t* bh, uint8_t* bl, uint32_t sw, float4 v) {
    float vv[4] = {v.x, v.y, v.z, v.w};
    uint32_t h[4], l[4];
#pragma unroll
    for (int q = 0; q < 4; q++) {
        __half hh = __float2half_rn(vv[q]);
        __half ll = __float2half_rn(vv[q] - __half2float(hh));
        h[q] = (uint32_t)__half_as_ushort(hh);
        l[q] = (uint32_t)__half_as_ushort(ll);
    }
    *(uint2*)(bh + sw) = make_uint2(h[0] | (h[1] << 16), h[2] | (h[3] << 16));
    *(uint2*)(bl + sw) = make_uint2(l[0] | (l[1] << 16), l[2] | (l[3] << 16));
}

struct PWJob { const float* W; __half* Dh; __half* Dl; int N, K, nblks, kblks, blk0, cnt; };
struct PWJobs { PWJob j[6]; };

__global__ void prepack_w_all(PWJobs jobs) {
    int b = blockIdx.x;
#pragma unroll 1
    for (int ji = 0; ji < 6; ji++) {
        const PWJob& J = jobs.j[ji];
        if (b < J.blk0 || b >= J.blk0 + J.cnt) continue;
        int t = b - J.blk0;
        int kb = t % J.kblks, nb = (t / J.kblks) % J.nblks, e = t / (J.kblks * J.nblks);
        const float* src = J.W + (size_t)e * J.N * J.K;
        uint8_t* bh = (uint8_t*)(J.Dh + (size_t)t * 4096);
        uint8_t* bl = (uint8_t*)(J.Dl + (size_t)t * 4096);
        for (int i = threadIdx.x; i < 1024; i += 256) {
            int r = i >> 4, c4 = i & 15;
            int n = nb * 64 + r, k = kb * 64 + c4 * 4;
            float4 v = make_float4(0.f, 0.f, 0.f, 0.f);
            if (n < J.N && k < J.K) v = *(const float4*)(src + (size_t)n * J.K + k);
            split_store(bh, bl, SWZ((uint32_t)(r * 128 + c4 * 8)), v);
        }
        return;
    }
}

__global__ void prepack_a_all(const float* __restrict__ x, const float* __restrict__ z) {
    int b = blockIdx.x;
    if (b < MBK * 5) {
        int kb = b % 5, mb = b / 5;
        uint8_t* bh = (uint8_t*)(g_A0h + (size_t)b * 8192);
        uint8_t* bl = (uint8_t*)(g_A0l + (size_t)b * 8192);
        for (int i = threadIdx.x; i < 2048; i += 256) {
            int r = i >> 4, c4 = i & 15;
            int row = mb * 128 + r, k = kb * 64 + c4 * 4;
            float4 v;
            if (k < D3) v = *(const float4*)(x + (size_t)row * D3 + k);
            else        v = *(const float4*)(z + (size_t)row * LZ + (k - D3));
            split_store(bh, bl, SWZ((uint32_t)(r * 128 + c4 * 8)), v);
        }
    } else {
        int mb = b - MBK * 5;
        size_t off = ((size_t)mb * 9 + 8) * 8192;
        for (int i = threadIdx.x; i < 2048; i += 256) {
            int r = i >> 4, c4 = i & 15;
            int row = mb * 128 + r, k = c4 * 4;
            float4 v = make_float4(0.f, 0.f, 0.f, 0.f);
            if (k < LZ) v = *(const float4*)(z + (size_t)row * LZ + k);
            uint32_t sw = SWZ((uint32_t)(r * 128 + c4 * 8));
            split_store((uint8_t*)(g_A1h + off), (uint8_t*)(g_A1l + off), sw, v);
            split_store((uint8_t*)(g_A2h + off), (uint8_t*)(g_A2l + off), sw, v);
        }
    }
}

// ---------------- gating logits + softmax (warp-per-row, smem-staged gW3) ----------------
__global__ void logits_softmax(const float* __restrict__ h2,
                               const float* __restrict__ gW3,
                               const float* __restrict__ gb3) {
    __shared__ float ws[8][128];
    __shared__ float bsm[8];
    int tid = threadIdx.x, lane = tid & 31, w = tid >> 5;
    for (int i = tid; i < 8 * 128; i += 256) ws[i >> 7][i & 127] = gW3[i];
    if (tid < 8) bsm[tid] = gb3[tid];
    __syncthreads();
    int row = blockIdx.x * 8 + w;
    float4 v = ((const float4*)(h2 + (size_t)row * GHD))[lane];
    float p[8];
#pragma unroll
    for (int e = 0; e < 8; e++) {
        float4 wv = ((const float4*)ws[e])[lane];
        p[e] = v.x*wv.x + v.y*wv.y + v.z*wv.z + v.w*wv.w;
    }
#pragma unroll
    for (int o = 16; o; o >>= 1)
#pragma unroll
        for (int e = 0; e < 8; e++) p[e] += __shfl_xor_sync(0xffffffffu, p[e], o);
    if (lane < 8) {
        float m = -1e30f;
#pragma unroll
        for (int e = 0; e < 8; e++) { p[e] += bsm[e]; m = fmaxf(m, p[e]); }
        float Z = 0.f;
#pragma unroll
        for (int e = 0; e < 8; e++) Z += expf(p[e] - m);
        float myp = p[0];
#pragma unroll
        for (int e = 1; e < 8; e++) myp = (lane == e) ? p[e] : myp;
        g_gate[row * 8 + lane] = expf(myp - m) / Z;
    }
}

// ---------------- host ----------------
static constexpr int SMEM_W3 = 32768 + 4*16384 + 2048 + 2048 + 256;  // 102656 (WLO=true)
static constexpr int SMEM_W2 = 32768 + 4*8192  + 2048 + 2048 + 256;  // 69888  (WLO=false)

extern "C" void kernel_launch(void* const* d_in, const int* in_sizes, int n_in,
                              void* d_out, int out_size) {
    const float* x   = (const float*)d_in[0];
    const float* z   = (const float*)d_in[1];
    const float* W0  = (const float*)d_in[2];
    const float* b0  = (const float*)d_in[3];
    const float* W1  = (const float*)d_in[4];
    const float* b1  = (const float*)d_in[5];
    const float* W2  = (const float*)d_in[6];
    const float* b2  = (const float*)d_in[7];
    const float* W3  = (const float*)d_in[8];
    const float* b3  = (const float*)d_in[9];
    const float* gW1 = (const float*)d_in[10];
    const float* gb1 = (const float*)d_in[11];
    const float* gW2 = (const float*)d_in[12];
    const float* gb2 = (const float*)d_in[13];
    const float* gW3 = (const float*)d_in[14];
    const float* gb3 = (const float*)d_in[15];
    float* out = (float*)d_out;
    (void)in_sizes; (void)n_in; (void)out_size;

    __half *A0h,*A0l,*A1h,*A1l,*A2h,*A2l,*A3h,*A3l,*G1h,*G1l;
    __half *pW0h,*pW0l,*pW1h,*pW1l,*pW2h,*pW2l,*pW3h,*pW3l,*pg1h,*pg1l,*pg2h,*pg2l;
    float *gh2, *gate;
    cudaGetSymbolAddress((void**)&A0h, g_A0h); cudaGetSymbolAddress((void**)&A0l, g_A0l);
    cudaGetSymbolAddress((void**)&A1h, g_A1h); cudaGetSymbolAddress((void**)&A1l, g_A1l);
    cudaGetSymbolAddress((void**)&A2h, g_A2h); cudaGetSymbolAddress((void**)&A2l, g_A2l);
    cudaGetSymbolAddress((void**)&A3h, g_A3h); cudaGetSymbolAddress((void**)&A3l, g_A3l);
    cudaGetSymbolAddress((void**)&G1h, g_G1h); cudaGetSymbolAddress((void**)&G1l, g_G1l);
    cudaGetSymbolAddress((void**)&pW0h, g_W0h); cudaGetSymbolAddress((void**)&pW0l, g_W0l);
    cudaGetSymbolAddress((void**)&pW1h, g_W1h); cudaGetSymbolAddress((void**)&pW1l, g_W1l);
    cudaGetSymbolAddress((void**)&pW2h, g_W2h); cudaGetSymbolAddress((void**)&pW2l, g_W2l);
    cudaGetSymbolAddress((void**)&pW3h, g_W3h); cudaGetSymbolAddress((void**)&pW3l, g_W3l);
    cudaGetSymbolAddress((void**)&pg1h, g_gW1h); cudaGetSymbolAddress((void**)&pg1l, g_gW1l);
    cudaGetSymbolAddress((void**)&pg2h, g_gW2h); cudaGetSymbolAddress((void**)&pg2l, g_gW2l);
    cudaGetSymbolAddress((void**)&gh2, g_gh2); cudaGetSymbolAddress((void**)&gate, g_gate);

    cudaFuncSetAttribute(moe_gemm<1,false,true,false,true>, cudaFuncAttributeMaxDynamicSharedMemorySize, SMEM_W3);
    cudaFuncSetAttribute(moe_gemm<1,false,true,true,true>,  cudaFuncAttributeMaxDynamicSharedMemorySize, SMEM_W3);
    cudaFuncSetAttribute(moe_gemm<8,true,true,false,true>,  cudaFuncAttributeMaxDynamicSharedMemorySize, SMEM_W3);
    cudaFuncSetAttribute(moe_gemm<8,true,true,false,false>, cudaFuncAttributeMaxDynamicSharedMemorySize, SMEM_W2);
    cudaFuncSetAttribute(moe_gemm<8,true,false,true,false>, cudaFuncAttributeMaxDynamicSharedMemorySize, SMEM_W2);

    // prepack weights (one launch) + inputs (one launch)
    PWJobs jobs;
    jobs.j[0] = {W0,  pW0h, pW0l, HH,  320, 8, 5, 0,    320};
    jobs.j[1] = {W1,  pW1h, pW1l, HH,  544, 8, 9, 320,  576};
    jobs.j[2] = {W2,  pW2h, pW2l, HH,  544, 8, 9, 896,  576};
    jobs.j[3] = {W3,  pW3h, pW3l, OO,  512, 2, 8, 1472, 128};
    jobs.j[4] = {gW1, pg1h, pg1l, GHD, 320, 2, 5, 1600, 10};
    jobs.j[5] = {gW2, pg2h, pg2l, GHD, GHD, 2, 2, 1610, 4};
    prepack_w_all<<<1614, 256>>>(jobs);
    prepack_a_all<<<MBK*5 + MBK, 256>>>(x, z);

    // gating MLP (3-term, M64 tiles)
    moe_gemm<1,false,true,false,true><<<dim3(2, 64), 160, SMEM_W3>>>(
        A0h, A0l, 5, pg1h, pg1l, 2, gb1, nullptr, GHD, G1h, G1l, 2, nullptr, 0);
    moe_gemm<1,false,true,true,true><<<dim3(2, 64), 160, SMEM_W3>>>(
        G1h, G1l, 2, pg2h, pg2l, 2, gb2, nullptr, GHD, nullptr, nullptr, 0, gh2, GHD);
    logits_softmax<<<BB/8, 256>>>(gh2, gW3, gb3);

    // blended expert layers: L0 3-term, L1-L3 2-term (drop W-lo correction)
    moe_gemm<8,true,true,false,true><<<dim3(8, 64), 160, SMEM_W3>>>(
        A0h, A0l, 5, pW0h, pW0l, 8, b0, gate, HH, A1h, A1l, 9, nullptr, 0);
    moe_gemm<8,true,true,false,false><<<dim3(8, 64), 160, SMEM_W2>>>(
        A1h, A1l, 9, pW1h, pW1l, 8, b1, gate, HH, A2h, A2l, 9, nullptr, 0);
    moe_gemm<8,true,true,false,false><<<dim3(8, 64), 160, SMEM_W2>>>(
        A2h, A2l, 9, pW2h, pW2l, 8, b2, gate, HH, A3h, A3l, 8, nullptr, 0);
    moe_gemm<8,true,false,true,false><<<dim3(2, 64), 160, SMEM_W2>>>(
        A3h, A3l, 8, pW3h, pW3l, 2, b3, gate, OO, nullptr, nullptr, 0, out, OO);
}

// round 16
// speedup vs baseline: 4.2214x; 1.0621x over previous
#include <cuda_runtime.h>
#include <cuda_fp16.h>
#include <math.h>
#include <stdint.h>

// ---------------- problem constants ----------------
static constexpr int BB=4096, D3=288, LZ=32, HH=512, OO=96, EE=8, GHD=128;
static constexpr int MBK = BB/128;   // 32 m-blocks (128-row blobs)

#define SWZ(o) ((o) ^ (((o) >> 3) & 0x70))

// ---------------- global scratch (pre-swizzled SW128 blobs; no allocs allowed) ----------------
// A blobs: [mblk128][kblk] tiles of 128 rows x 64 half cols = 8192 halves = 16KB
// W blobs: [e][nblk][kblk] tiles of 64 rows x 64 half cols = 4096 halves = 8KB
__device__ __align__(128) __half g_A0h[MBK*5*8192], g_A0l[MBK*5*8192];
__device__ __align__(128) __half g_A1h[MBK*9*8192], g_A1l[MBK*9*8192];
__device__ __align__(128) __half g_A2h[MBK*9*8192], g_A2l[MBK*9*8192];
__device__ __align__(128) __half g_A3h[MBK*8*8192], g_A3l[MBK*8*8192];
__device__ __align__(128) __half g_G1h[MBK*2*8192], g_G1l[MBK*2*8192];
__device__ __align__(128) __half g_W0h[8*8*5*4096], g_W0l[8*8*5*4096];
__device__ __align__(128) __half g_W1h[8*8*9*4096], g_W1l[8*8*9*4096];
__device__ __align__(128) __half g_W2h[8*8*9*4096], g_W2l[8*8*9*4096];
__device__ __align__(128) __half g_W3h[8*2*8*4096], g_W3l[8*2*8*4096];
__device__ __align__(128) __half g_gW1h[2*5*4096],  g_gW1l[2*5*4096];
__device__ __align__(128) __half g_gW2h[2*2*4096],  g_gW2l[2*2*4096];
__device__ float g_gh2[BB*GHD];
__device__ float g_gate[BB*EE];

// ---------------- PTX helpers ----------------
__device__ __forceinline__ uint32_t smem_u32(const void* p) {
    uint32_t a;
    asm("{ .reg .u64 t; cvta.to.shared.u64 t, %1; cvt.u32.u64 %0, t; }" : "=r"(a) : "l"(p));
    return a;
}
__device__ __forceinline__ void mbar_init(uint32_t m, uint32_t c) {
    asm volatile("mbarrier.init.shared.b64 [%0], %1;" :: "r"(m), "r"(c) : "memory");
}
__device__ __forceinline__ void mbar_expect(uint32_t m, uint32_t b) {
    asm volatile("mbarrier.arrive.expect_tx.shared.b64 _, [%0], %1;" :: "r"(m), "r"(b) : "memory");
}
__device__ __forceinline__ void mbar_arrive(uint32_t m) {
    asm volatile("mbarrier.arrive.shared.b64 _, [%0];" :: "r"(m) : "memory");
}
__device__ __forceinline__ void mbar_wait(uint32_t m, uint32_t ph) {
    uint32_t done;
    asm volatile("{\n\t.reg .pred p;\n\t"
        "mbarrier.try_wait.parity.acquire.cta.shared::cta.b64 p, [%1], %2;\n\t"
        "selp.b32 %0, 1, 0, p;\n\t}" : "=r"(done) : "r"(m), "r"(ph) : "memory");
    while (!done) {
        asm volatile("{\n\t.reg .pred p;\n\t"
            "mbarrier.try_wait.parity.acquire.cta.shared::cta.b64 p, [%1], %2, 0x989680;\n\t"
            "selp.b32 %0, 1, 0, p;\n\t}" : "=r"(done) : "r"(m), "r"(ph) : "memory");
    }
}
__device__ __forceinline__ void bulk_g2s(uint32_t dst, const void* src, uint32_t bytes, uint32_t mbar) {
    asm volatile("cp.async.bulk.shared::cluster.global.mbarrier::complete_tx::bytes [%0], [%1], %2, [%3];"
        :: "r"(dst), "l"(src), "r"(bytes), "r"(mbar) : "memory");
}
__device__ __forceinline__ void ldm_x4(uint32_t* r, uint32_t addr) {
    asm volatile("ldmatrix.sync.aligned.m8n8.x4.shared.b16 {%0,%1,%2,%3}, [%4];"
        : "=r"(r[0]), "=r"(r[1]), "=r"(r[2]), "=r"(r[3]) : "r"(addr));
}
__device__ __forceinline__ void mma16816(float* d, const uint32_t* a, uint32_t b0, uint32_t b1) {
    asm("mma.sync.aligned.m16n8k16.row.col.f32.f16.f16.f32 "
        "{%0,%1,%2,%3}, {%4,%5,%6,%7}, {%8,%9}, {%0,%1,%2,%3};"
        : "+f"(d[0]), "+f"(d[1]), "+f"(d[2]), "+f"(d[3])
        : "r"(a[0]), "r"(a[1]), "r"(a[2]), "r"(a[3]), "r"(b0), "r"(b1));
}
__device__ __forceinline__ float elu1(float x) { return x > 0.f ? x : expm1f(x); }

// ---------------- blended expert GEMM (mma.sync HMMA, fp16 split, f32 acc) ----------------
// BM=64 (2 m-warps), BN=64 (2 n-warps), 1 producer warp -> 160 threads, 2 CTAs/SM.
// WLO=true : 3 terms (Ah*Wh + Al*Wh + Ah*Wl), W slots 16KB (hi+lo).
// WLO=false: 2 terms (Ah*Wh + Al*Wh),          W slots  8KB (hi only).
template<int EXP, bool GATE, bool ACT, bool OUTF32, bool WLO>
__global__ void __launch_bounds__(160, 2) moe_gemm(
    const __half* __restrict__ Ah, const __half* __restrict__ Al, int kblks,
    const __half* __restrict__ Wh, const __half* __restrict__ Wl, int wnb,
    const float* __restrict__ bias, const float* __restrict__ gate, int ntot,
    __half* __restrict__ Oh, __half* __restrict__ Ol, int okb,
    float* __restrict__ C, int ldc)
{
    constexpr int MW = 2, CW = 4, NT = 160, BM = 64, WS = 4;
    constexpr int ABYTES = BM * 128;        // 8192
    constexpr int A_STG  = 2 * ABYTES;      // 16384 (A hi+lo always)
    constexpr int W_OFFc = 2 * A_STG;       // 32768
    constexpr int W_STRIDE = WLO ? 16384 : 8192;
    constexpr int GS_OFFc  = W_OFFc + WS * W_STRIDE;
    constexpr int BS_OFFc  = GS_OFFc + 2048;
    constexpr int BAR_OFFc = BS_OFFc + 2048;

    extern __shared__ __align__(1024) uint8_t smem[];
    const uint32_t sb = smem_u32(smem);
    const int tid = threadIdx.x;
    const int lane = tid & 31, wid = tid >> 5;
    const int wm = wid % MW, wn = (wid / MW) & 1;
    const int mblk = blockIdx.y, nblk = blockIdx.x;

    const uint32_t bAf = sb + BAR_OFFc;          // 2 x 8B
    const uint32_t bAe = sb + BAR_OFFc + 16;     // 2 x 8B
    const uint32_t bWf = sb + BAR_OFFc + 32;     // 4 x 8B
    const uint32_t bWe = sb + BAR_OFFc + 64;     // 4 x 8B

    if (tid == 0) {
        for (int s = 0; s < 2; s++)  { mbar_init(bAf + s*8, 1); mbar_init(bAe + s*8, CW); }
        for (int s = 0; s < WS; s++) { mbar_init(bWf + s*8, 1); mbar_init(bWe + s*8, CW); }
    }
    float* gS = (float*)(smem + GS_OFFc);
    float* bS = (float*)(smem + BS_OFFc);
    if (GATE) {
        for (int i = tid; i < BM * EE; i += NT) gS[i] = gate[(size_t)mblk * BM * EE + i];
    }
    for (int i = tid; i < EXP * 64; i += NT) {
        int e = i >> 6, j = i & 63, o = nblk * 64 + j;
        bS[i] = (o < ntot) ? bias[e * ntot + o] : 0.f;
    }
    __syncthreads();

    if (wid == CW) {
        // ---------------- dedicated producer warp (lane 0 only) ----------------
        if (lane == 0) {
            for (int kb = 0; kb < kblks; kb++) {
                int as = kb & 1;
                if (kb >= 2) mbar_wait(bAe + as*8, ((kb >> 1) & 1) ^ 1);
                mbar_expect(bAf + as*8, 2 * ABYTES);
                // blobs hold 128 rows; BM=64 tile is the (mblk&1) half
                size_t aoff = ((size_t)(mblk >> 1) * kblks + kb) * 8192 + (size_t)(mblk & 1) * 4096;
                bulk_g2s(sb + as*A_STG,          Ah + aoff, ABYTES, bAf + as*8);
                bulk_g2s(sb + as*A_STG + ABYTES, Al + aoff, ABYTES, bAf + as*8);
                for (int e = 0; e < EXP; e++) {
                    int wu = kb * EXP + e, s = wu & (WS - 1);
                    if (wu >= WS) mbar_wait(bWe + s*8, ((wu / WS) & 1) ^ 1);
                    mbar_expect(bWf + s*8, WLO ? 16384 : 8192);
                    size_t woff = (((size_t)e * wnb + nblk) * kblks + kb) * 4096;
                    bulk_g2s(sb + W_OFFc + s*W_STRIDE, Wh + woff, 8192, bWf + s*8);
                    if (WLO)
                        bulk_g2s(sb + W_OFFc + s*W_STRIDE + 8192, Wl + woff, 8192, bWf + s*8);
                }
            }
        }
        return;
    }

    // ---------------- compute warps (0-3) ----------------
    uint32_t offA[2][4], offB[2][4];
#pragma unroll
    for (int i = 0; i < 2; i++)
#pragma unroll
        for (int j = 0; j < 4; j++)
            offA[i][j] = SWZ((uint32_t)((wm*32 + i*16 + (lane & 15)) * 128 + j*32 + (lane >> 4) * 16));
#pragma unroll
    for (int p = 0; p < 2; p++)
#pragma unroll
        for (int j = 0; j < 4; j++)
            offB[p][j] = SWZ((uint32_t)((wn*32 + p*16 + (lane & 15)) * 128 + j*32 + (lane >> 4) * 16));

    float acc[2][4][4];
#pragma unroll
    for (int i = 0; i < 2; i++)
#pragma unroll
        for (int n8 = 0; n8 < 4; n8++)
#pragma unroll
            for (int q = 0; q < 4; q++) acc[i][n8][q] = 0.f;

    int wu = 0;
#pragma unroll 1
    for (int kb = 0; kb < kblks; kb++) {
        int as = kb & 1;
        mbar_wait(bAf + as*8, (kb >> 1) & 1);
        const uint32_t Ab = sb + as*A_STG;
        uint32_t aH[2][4][4], aL[2][4][4];   // A fragments resident across expert loop
#pragma unroll
        for (int i = 0; i < 2; i++)
#pragma unroll
            for (int j = 0; j < 4; j++) {
                ldm_x4(aH[i][j], Ab + offA[i][j]);
                ldm_x4(aL[i][j], Ab + ABYTES + offA[i][j]);
            }
        if (lane == 0) mbar_arrive(bAe + as*8);
#pragma unroll 1
        for (int e = 0; e < EXP; e++) {
            int s = wu & (WS - 1);
            mbar_wait(bWf + s*8, (wu / WS) & 1);
            const uint32_t Wb = sb + W_OFFc + s*W_STRIDE;
            if (GATE) {
                float part[2][4][4];
#pragma unroll
                for (int i = 0; i < 2; i++)
#pragma unroll
                    for (int n8 = 0; n8 < 4; n8++)
#pragma unroll
                        for (int q = 0; q < 4; q++) part[i][n8][q] = 0.f;
#pragma unroll
                for (int j = 0; j < 4; j++) {
                    uint32_t b0h[4], b1h[4], b0l[4], b1l[4];
                    ldm_x4(b0h, Wb + offB[0][j]);
                    ldm_x4(b1h, Wb + offB[1][j]);
                    if (WLO) {
                        ldm_x4(b0l, Wb + 8192 + offB[0][j]);
                        ldm_x4(b1l, Wb + 8192 + offB[1][j]);
                    }
#pragma unroll
                    for (int i = 0; i < 2; i++)
#pragma unroll
                        for (int n8 = 0; n8 < 4; n8++) {
                            const uint32_t* bh = (n8 < 2) ? b0h : b1h;
                            int q = n8 & 1;
                            mma16816(part[i][n8], aH[i][j], bh[q], bh[2 + q]);
                            mma16816(part[i][n8], aL[i][j], bh[q], bh[2 + q]);
                            if (WLO) {
                                const uint32_t* bl = (n8 < 2) ? b0l : b1l;
                                mma16816(part[i][n8], aH[i][j], bl[q], bl[2 + q]);
                            }
                        }
                }
                if (lane == 0) mbar_arrive(bWe + s*8);
                int r0 = wm*32 + (lane >> 2);
                float g0 = gS[(r0 + 0)  * EE + e], g1 = gS[(r0 + 8)  * EE + e];
                float g2 = gS[(r0 + 16) * EE + e], g3 = gS[(r0 + 24) * EE + e];
#pragma unroll
                for (int n8 = 0; n8 < 4; n8++) {
                    acc[0][n8][0] += g0 * part[0][n8][0];
                    acc[0][n8][1] += g0 * part[0][n8][1];
                    acc[0][n8][2] += g1 * part[0][n8][2];
                    acc[0][n8][3] += g1 * part[0][n8][3];
                    acc[1][n8][0] += g2 * part[1][n8][0];
                    acc[1][n8][1] += g2 * part[1][n8][1];
                    acc[1][n8][2] += g3 * part[1][n8][2];
                    acc[1][n8][3] += g3 * part[1][n8][3];
                }
            } else {
#pragma unroll
                for (int j = 0; j < 4; j++) {
                    uint32_t b0h[4], b1h[4], b0l[4], b1l[4];
                    ldm_x4(b0h, Wb + offB[0][j]);
                    ldm_x4(b1h, Wb + offB[1][j]);
                    if (WLO) {
                        ldm_x4(b0l, Wb + 8192 + offB[0][j]);
                        ldm_x4(b1l, Wb + 8192 + offB[1][j]);
                    }
#pragma unroll
                    for (int i = 0; i < 2; i++)
#pragma unroll
                        for (int n8 = 0; n8 < 4; n8++) {
                            const uint32_t* bh = (n8 < 2) ? b0h : b1h;
                            int q = n8 & 1;
                            mma16816(acc[i][n8], aH[i][j], bh[q], bh[2 + q]);
                            mma16816(acc[i][n8], aL[i][j], bh[q], bh[2 + q]);
                            if (WLO) {
                                const uint32_t* bl = (n8 < 2) ? b0l : b1l;
                                mma16816(acc[i][n8], aH[i][j], bl[q], bl[2 + q]);
                            }
                        }
                }
                if (lane == 0) mbar_arrive(bWe + s*8);
            }
            wu++;
        }
    }

    // ---- epilogue: blended bias + activation + store ----
    const int rbase = wm*32 + (lane >> 2);
    const int cbase = wn*32 + (lane & 3) * 2;
#pragma unroll
    for (int i = 0; i < 2; i++) {
#pragma unroll
        for (int hf = 0; hf < 2; hf++) {
            int lr = rbase + i*16 + hf*8;
            int gr = mblk*BM + lr;
#pragma unroll
            for (int n8 = 0; n8 < 4; n8++) {
                int cl = cbase + n8*8;
                float v0 = acc[i][n8][hf*2 + 0];
                float v1 = acc[i][n8][hf*2 + 1];
                if (GATE) {
                    float s0 = 0.f, s1 = 0.f;
#pragma unroll
                    for (int e = 0; e < EXP; e++) {
                        float g = gS[lr * EE + e];
                        s0 += g * bS[e*64 + cl];
                        s1 += g * bS[e*64 + cl + 1];
                    }
                    v0 += s0; v1 += s1;
                } else { v0 += bS[cl]; v1 += bS[cl + 1]; }
                if (ACT) { v0 = elu1(v0); v1 = elu1(v1); }
                if (OUTF32) {
                    int c = nblk*64 + cl;
                    if (c < ntot)     C[(size_t)gr * ldc + c]     = v0;
                    if (c + 1 < ntot) C[(size_t)gr * ldc + c + 1] = v1;
                } else {
                    __half h0 = __float2half_rn(v0), h1 = __float2half_rn(v1);
                    __half l0 = __float2half_rn(v0 - __half2float(h0));
                    __half l1 = __float2half_rn(v1 - __half2float(h1));
                    int gcol = nblk*64 + cl;
                    uint32_t off = SWZ((uint32_t)((gr & 127) * 128 + (gcol & 63) * 2));
                    size_t bidx = ((size_t)(gr >> 7) * okb + (gcol >> 6)) * 8192;
                    *(__half2*)((uint8_t*)(Oh + bidx) + off) = __halves2half2(h0, h1);
                    *(__half2*)((uint8_t*)(Ol + bidx) + off) = __halves2half2(l0, l1);
                }
            }
        }
    }
}

// ---------------- prepack: fp32 -> fp16 hi/lo split, SW128-swizzled blobs ----------------
__device__ __forceinline__ void split_store(uint8_t* bh, uint8_t* bl, uint32_t sw, float4 v) {
    float vv[4] = {v.x, v.y, v.z, v.w};
    uint32_t h[4], l[4];
#pragma unroll
    for (int q = 0; q < 4; q++) {
        __half hh = __float2half_rn(vv[q]);
        __half ll = __float2half_rn(vv[q] - __half2float(hh));
        h[q] = (uint32_t)__half_as_ushort(hh);
        l[q] = (uint32_t)__half_as_ushort(ll);
    }
    *(uint2*)(bh + sw) = make_uint2(h[0] | (h[1] << 16), h[2] | (h[3] << 16));
    *(uint2*)(bl + sw) = make_uint2(l[0] | (l[1] << 16), l[2] | (l[3] << 16));
}

struct PWJob { const float* W; __half* Dh; __half* Dl; int N, K, nblks, kblks, blk0, cnt; };
struct PWJobs { PWJob j[6]; };

__global__ void prepack_w_all(PWJobs jobs) {
    int b = blockIdx.x;
#pragma unroll 1
    for (int ji = 0; ji < 6; ji++) {
        const PWJob& J = jobs.j[ji];
        if (b < J.blk0 || b >= J.blk0 + J.cnt) continue;
        int t = b - J.blk0;
        int kb = t % J.kblks, nb = (t / J.kblks) % J.nblks, e = t / (J.kblks * J.nblks);
        const float* src = J.W + (size_t)e * J.N * J.K;
        uint8_t* bh = (uint8_t*)(J.Dh + (size_t)t * 4096);
        uint8_t* bl = (uint8_t*)(J.Dl + (size_t)t * 4096);
        for (int i = threadIdx.x; i < 1024; i += 256) {
            int r = i >> 4, c4 = i & 15;
            int n = nb * 64 + r, k = kb * 64 + c4 * 4;
            float4 v = make_float4(0.f, 0.f, 0.f, 0.f);
            if (n < J.N && k < J.K) v = *(const float4*)(src + (size_t)n * J.K + k);
            split_store(bh, bl, SWZ((uint32_t)(r * 128 + c4 * 8)), v);
        }
        return;
    }
}

__global__ void prepack_a_all(const float* __restrict__ x, const float* __restrict__ z) {
    int b = blockIdx.x;
    if (b < MBK * 5) {
        int kb = b % 5, mb = b / 5;
        uint8_t* bh = (uint8_t*)(g_A0h + (size_t)b * 8192);
        uint8_t* bl = (uint8_t*)(g_A0l + (size_t)b * 8192);
        for (int i = threadIdx.x; i < 2048; i += 256) {
            int r = i >> 4, c4 = i & 15;
            int row = mb * 128 + r, k = kb * 64 + c4 * 4;
            float4 v;
            if (k < D3) v = *(const float4*)(x + (size_t)row * D3 + k);
            else        v = *(const float4*)(z + (size_t)row * LZ + (k - D3));
            split_store(bh, bl, SWZ((uint32_t)(r * 128 + c4 * 8)), v);
        }
    } else {
        int mb = b - MBK * 5;
        size_t off = ((size_t)mb * 9 + 8) * 8192;
        for (int i = threadIdx.x; i < 2048; i += 256) {
            int r = i >> 4, c4 = i & 15;
            int row = mb * 128 + r, k = c4 * 4;
            float4 v = make_float4(0.f, 0.f, 0.f, 0.f);
            if (k < LZ) v = *(const float4*)(z + (size_t)row * LZ + k);
            uint32_t sw = SWZ((uint32_t)(r * 128 + c4 * 8));
            split_store((uint8_t*)(g_A1h + off), (uint8_t*)(g_A1l + off), sw, v);
            split_store((uint8_t*)(g_A2h + off), (uint8_t*)(g_A2l + off), sw, v);
        }
    }
}

// ---------------- gating logits + softmax (warp-per-row, smem-staged gW3) ----------------
__global__ void logits_softmax(const float* __restrict__ h2,
                               const float* __restrict__ gW3,
                               const float* __restrict__ gb3) {
    __shared__ float ws[8][128];
    __shared__ float bsm[8];
    int tid = threadIdx.x, lane = tid & 31, w = tid >> 5;
    for (int i = tid; i < 8 * 128; i += 256) ws[i >> 7][i & 127] = gW3[i];
    if (tid < 8) bsm[tid] = gb3[tid];
    __syncthreads();
    int row = blockIdx.x * 8 + w;
    float4 v = ((const float4*)(h2 + (size_t)row * GHD))[lane];
    float p[8];
#pragma unroll
    for (int e = 0; e < 8; e++) {
        float4 wv = ((const float4*)ws[e])[lane];
        p[e] = v.x*wv.x + v.y*wv.y + v.z*wv.z + v.w*wv.w;
    }
#pragma unroll
    for (int o = 16; o; o >>= 1)
#pragma unroll
        for (int e = 0; e < 8; e++) p[e] += __shfl_xor_sync(0xffffffffu, p[e], o);
    if (lane < 8) {
        float m = -1e30f;
#pragma unroll
        for (int e = 0; e < 8; e++) { p[e] += bsm[e]; m = fmaxf(m, p[e]); }
        float Z = 0.f;
#pragma unroll
        for (int e = 0; e < 8; e++) Z += expf(p[e] - m);
        float myp = p[0];
#pragma unroll
        for (int e = 1; e < 8; e++) myp = (lane == e) ? p[e] : myp;
        g_gate[row * 8 + lane] = expf(myp - m) / Z;
    }
}

// ---------------- host ----------------
static constexpr int SMEM_W3 = 32768 + 4*16384 + 2048 + 2048 + 256;  // 102656 (WLO=true)
static constexpr int SMEM_W2 = 32768 + 4*8192  + 2048 + 2048 + 256;  // 69888  (WLO=false)

extern "C" void kernel_launch(void* const* d_in, const int* in_sizes, int n_in,
                              void* d_out, int out_size) {
    const float* x   = (const float*)d_in[0];
    const float* z   = (const float*)d_in[1];
    const float* W0  = (const float*)d_in[2];
    const float* b0  = (const float*)d_in[3];
    const float* W1  = (const float*)d_in[4];
    const float* b1  = (const float*)d_in[5];
    const float* W2  = (const float*)d_in[6];
    const float* b2  = (const float*)d_in[7];
    const float* W3  = (const float*)d_in[8];
    const float* b3  = (const float*)d_in[9];
    const float* gW1 = (const float*)d_in[10];
    const float* gb1 = (const float*)d_in[11];
    const float* gW2 = (const float*)d_in[12];
    const float* gb2 = (const float*)d_in[13];
    const float* gW3 = (const float*)d_in[14];
    const float* gb3 = (const float*)d_in[15];
    float* out = (float*)d_out;
    (void)in_sizes; (void)n_in; (void)out_size;

    __half *A0h,*A0l,*A1h,*A1l,*A2h,*A2l,*A3h,*A3l,*G1h,*G1l;
    __half *pW0h,*pW0l,*pW1h,*pW1l,*pW2h,*pW2l,*pW3h,*pW3l,*pg1h,*pg1l,*pg2h,*pg2l;
    float *gh2, *gate;
    cudaGetSymbolAddress((void**)&A0h, g_A0h); cudaGetSymbolAddress((void**)&A0l, g_A0l);
    cudaGetSymbolAddress((void**)&A1h, g_A1h); cudaGetSymbolAddress((void**)&A1l, g_A1l);
    cudaGetSymbolAddress((void**)&A2h, g_A2h); cudaGetSymbolAddress((void**)&A2l, g_A2l);
    cudaGetSymbolAddress((void**)&A3h, g_A3h); cudaGetSymbolAddress((void**)&A3l, g_A3l);
    cudaGetSymbolAddress((void**)&G1h, g_G1h); cudaGetSymbolAddress((void**)&G1l, g_G1l);
    cudaGetSymbolAddress((void**)&pW0h, g_W0h); cudaGetSymbolAddress((void**)&pW0l, g_W0l);
    cudaGetSymbolAddress((void**)&pW1h, g_W1h); cudaGetSymbolAddress((void**)&pW1l, g_W1l);
    cudaGetSymbolAddress((void**)&pW2h, g_W2h); cudaGetSymbolAddress((void**)&pW2l, g_W2l);
    cudaGetSymbolAddress((void**)&pW3h, g_W3h); cudaGetSymbolAddress((void**)&pW3l, g_W3l);
    cudaGetSymbolAddress((void**)&pg1h, g_gW1h); cudaGetSymbolAddress((void**)&pg1l, g_gW1l);
    cudaGetSymbolAddress((void**)&pg2h, g_gW2h); cudaGetSymbolAddress((void**)&pg2l, g_gW2l);
    cudaGetSymbolAddress((void**)&gh2, g_gh2); cudaGetSymbolAddress((void**)&gate, g_gate);

    cudaFuncSetAttribute(moe_gemm<1,false,true,false,true>, cudaFuncAttributeMaxDynamicSharedMemorySize, SMEM_W3);
    cudaFuncSetAttribute(moe_gemm<1,false,true,true,true>,  cudaFuncAttributeMaxDynamicSharedMemorySize, SMEM_W3);
    cudaFuncSetAttribute(moe_gemm<8,true,true,false,false>, cudaFuncAttributeMaxDynamicSharedMemorySize, SMEM_W2);
    cudaFuncSetAttribute(moe_gemm<8,true,false,true,false>, cudaFuncAttributeMaxDynamicSharedMemorySize, SMEM_W2);

    // prepack weights (one launch) + inputs (one launch)
    PWJobs jobs;
    jobs.j[0] = {W0,  pW0h, pW0l, HH,  320, 8, 5, 0,    320};
    jobs.j[1] = {W1,  pW1h, pW1l, HH,  544, 8, 9, 320,  576};
    jobs.j[2] = {W2,  pW2h, pW2l, HH,  544, 8, 9, 896,  576};
    jobs.j[3] = {W3,  pW3h, pW3l, OO,  512, 2, 8, 1472, 128};
    jobs.j[4] = {gW1, pg1h, pg1l, GHD, 320, 2, 5, 1600, 10};
    jobs.j[5] = {gW2, pg2h, pg2l, GHD, GHD, 2, 2, 1610, 4};
    prepack_w_all<<<1614, 256>>>(jobs);
    prepack_a_all<<<MBK*5 + MBK, 256>>>(x, z);

    // gating MLP (3-term, M64 tiles) — kept full precision: softmax amplifies gate errors
    moe_gemm<1,false,true,false,true><<<dim3(2, 64), 160, SMEM_W3>>>(
        A0h, A0l, 5, pg1h, pg1l, 2, gb1, nullptr, GHD, G1h, G1l, 2, nullptr, 0);
    moe_gemm<1,false,true,true,true><<<dim3(2, 64), 160, SMEM_W3>>>(
        G1h, G1l, 2, pg2h, pg2l, 2, gb2, nullptr, GHD, nullptr, nullptr, 0, gh2, GHD);
    logits_softmax<<<BB/8, 256>>>(gh2, gW3, gb3);

    // blended expert layers: all 2-term (A hi/lo vs W hi only)
    moe_gemm<8,true,true,false,false><<<dim3(8, 64), 160, SMEM_W2>>>(
        A0h, A0l, 5, pW0h, pW0l, 8, b0, gate, HH, A1h, A1l, 9, nullptr, 0);
    moe_gemm<8,true,true,false,false><<<dim3(8, 64), 160, SMEM_W2>>>(
        A1h, A1l, 9, pW1h, pW1l, 8, b1, gate, HH, A2h, A2l, 9, nullptr, 0);
    moe_gemm<8,true,true,false,false><<<dim3(8, 64), 160, SMEM_W2>>>(
        A2h, A2l, 9, pW2h, pW2l, 8, b2, gate, HH, A3h, A3l, 8, nullptr, 0);
    moe_gemm<8,true,false,true,false><<<dim3(2, 64), 160, SMEM_W2>>>(
        A3h, A3l, 8, pW3h, pW3l, 2, b3, gate, OO, nullptr, nullptr, 0, out, OO);
}

// round 17
// speedup vs baseline: 6.0866x; 1.4418x over previous
#include <cuda_runtime.h>
#include <cuda_fp16.h>
#include <math.h>
#include <stdint.h>

// ---------------- problem constants ----------------
static constexpr int BB=4096, D3=288, LZ=32, HH=512, OO=96, EE=8, GHD=128;
static constexpr int MBK = BB/128;   // 32 m-blocks (128-row blobs)

#define SWZ(o) ((o) ^ (((o) >> 3) & 0x70))

// ---------------- global scratch (pre-swizzled SW128 blobs; no allocs allowed) ----------------
// A blobs: [mblk128][kblk] tiles of 128 rows x 64 half cols = 8192 halves = 16KB
// W blobs: [e][nblk][kblk] tiles of 64 rows x 64 half cols = 4096 halves = 8KB
__device__ __align__(128) __half g_A0h[MBK*5*8192], g_A0l[MBK*5*8192];
__device__ __align__(128) __half g_A1h[MBK*9*8192];
__device__ __align__(128) __half g_A2h[MBK*9*8192];
__device__ __align__(128) __half g_A3h[MBK*8*8192];
__device__ __align__(128) __half g_G1h[MBK*2*8192], g_G1l[MBK*2*8192];
__device__ __align__(128) __half g_W0h[8*8*5*4096];
__device__ __align__(128) __half g_W1h[8*8*9*4096];
__device__ __align__(128) __half g_W2h[8*8*9*4096];
__device__ __align__(128) __half g_W3h[8*2*8*4096];
__device__ __align__(128) __half g_gW1h[2*5*4096],  g_gW1l[2*5*4096];
__device__ __align__(128) __half g_gW2h[2*2*4096],  g_gW2l[2*2*4096];
__device__ float g_gh2[BB*GHD];
__device__ float g_gate[BB*EE];

// ---------------- PTX helpers ----------------
__device__ __forceinline__ uint32_t smem_u32(const void* p) {
    uint32_t a;
    asm("{ .reg .u64 t; cvta.to.shared.u64 t, %1; cvt.u32.u64 %0, t; }" : "=r"(a) : "l"(p));
    return a;
}
__device__ __forceinline__ void mbar_init(uint32_t m, uint32_t c) {
    asm volatile("mbarrier.init.shared.b64 [%0], %1;" :: "r"(m), "r"(c) : "memory");
}
__device__ __forceinline__ void mbar_expect(uint32_t m, uint32_t b) {
    asm volatile("mbarrier.arrive.expect_tx.shared.b64 _, [%0], %1;" :: "r"(m), "r"(b) : "memory");
}
__device__ __forceinline__ void mbar_arrive(uint32_t m) {
    asm volatile("mbarrier.arrive.shared.b64 _, [%0];" :: "r"(m) : "memory");
}
__device__ __forceinline__ void mbar_wait(uint32_t m, uint32_t ph) {
    uint32_t done;
    asm volatile("{\n\t.reg .pred p;\n\t"
        "mbarrier.try_wait.parity.acquire.cta.shared::cta.b64 p, [%1], %2;\n\t"
        "selp.b32 %0, 1, 0, p;\n\t}" : "=r"(done) : "r"(m), "r"(ph) : "memory");
    while (!done) {
        asm volatile("{\n\t.reg .pred p;\n\t"
            "mbarrier.try_wait.parity.acquire.cta.shared::cta.b64 p, [%1], %2, 0x989680;\n\t"
            "selp.b32 %0, 1, 0, p;\n\t}" : "=r"(done) : "r"(m), "r"(ph) : "memory");
    }
}
__device__ __forceinline__ void bulk_g2s(uint32_t dst, const void* src, uint32_t bytes, uint32_t mbar) {
    asm volatile("cp.async.bulk.shared::cluster.global.mbarrier::complete_tx::bytes [%0], [%1], %2, [%3];"
        :: "r"(dst), "l"(src), "r"(bytes), "r"(mbar) : "memory");
}
__device__ __forceinline__ void ldm_x4(uint32_t* r, uint32_t addr) {
    asm volatile("ldmatrix.sync.aligned.m8n8.x4.shared.b16 {%0,%1,%2,%3}, [%4];"
        : "=r"(r[0]), "=r"(r[1]), "=r"(r[2]), "=r"(r[3]) : "r"(addr));
}
__device__ __forceinline__ void mma16816(float* d, const uint32_t* a, uint32_t b0, uint32_t b1) {
    asm("mma.sync.aligned.m16n8k16.row.col.f32.f16.f16.f32 "
        "{%0,%1,%2,%3}, {%4,%5,%6,%7}, {%8,%9}, {%0,%1,%2,%3};"
        : "+f"(d[0]), "+f"(d[1]), "+f"(d[2]), "+f"(d[3])
        : "r"(a[0]), "r"(a[1]), "r"(a[2]), "r"(a[3]), "r"(b0), "r"(b1));
}
__device__ __forceinline__ float elu1(float x) { return x > 0.f ? x : expm1f(x); }

// ---------------- blended expert GEMM (mma.sync HMMA, fp16 split, f32 acc) ----------------
// BM=64 (2 m-warps), BN=64 (2 n-warps), 1 producer warp -> 160 threads, 2 CTAs/SM.
// Terms: Ah*Wh always; + Al*Wh if ALO; + Ah*Wl if WLO.
// OUTLO: write lo residual blob on split output (only needed if consumer uses ALO).
template<int EXP, bool GATE, bool ACT, bool OUTF32, bool WLO, bool ALO, bool OUTLO>
__global__ void __launch_bounds__(160, 2) moe_gemm(
    const __half* __restrict__ Ah, const __half* __restrict__ Al, int kblks,
    const __half* __restrict__ Wh, const __half* __restrict__ Wl, int wnb,
    const float* __restrict__ bias, const float* __restrict__ gate, int ntot,
    __half* __restrict__ Oh, __half* __restrict__ Ol, int okb,
    float* __restrict__ C, int ldc)
{
    constexpr int MW = 2, CW = 4, NT = 160, BM = 64, WS = 4;
    constexpr int ABYTES = BM * 128;                 // 8192 per A half-tile
    constexpr int A_STG  = (ALO ? 2 : 1) * ABYTES;   // per stage
    constexpr int W_OFFc = 2 * A_STG;
    constexpr int W_STRIDE = WLO ? 16384 : 8192;
    constexpr int GS_OFFc  = W_OFFc + WS * W_STRIDE;
    constexpr int BS_OFFc  = GS_OFFc + 2048;
    constexpr int BAR_OFFc = BS_OFFc + 2048;

    extern __shared__ __align__(1024) uint8_t smem[];
    const uint32_t sb = smem_u32(smem);
    const int tid = threadIdx.x;
    const int lane = tid & 31, wid = tid >> 5;
    const int wm = wid % MW, wn = (wid / MW) & 1;
    const int mblk = blockIdx.y, nblk = blockIdx.x;

    const uint32_t bAf = sb + BAR_OFFc;
    const uint32_t bAe = sb + BAR_OFFc + 16;
    const uint32_t bWf = sb + BAR_OFFc + 32;
    const uint32_t bWe = sb + BAR_OFFc + 64;

    if (tid == 0) {
        for (int s = 0; s < 2; s++)  { mbar_init(bAf + s*8, 1); mbar_init(bAe + s*8, CW); }
        for (int s = 0; s < WS; s++) { mbar_init(bWf + s*8, 1); mbar_init(bWe + s*8, CW); }
    }
    float* gS = (float*)(smem + GS_OFFc);
    float* bS = (float*)(smem + BS_OFFc);
    if (GATE) {
        for (int i = tid; i < BM * EE; i += NT) gS[i] = gate[(size_t)mblk * BM * EE + i];
    }
    for (int i = tid; i < EXP * 64; i += NT) {
        int e = i >> 6, j = i & 63, o = nblk * 64 + j;
        bS[i] = (o < ntot) ? bias[e * ntot + o] : 0.f;
    }
    __syncthreads();

    if (wid == CW) {
        // ---------------- dedicated producer warp (lane 0 only) ----------------
        if (lane == 0) {
            for (int kb = 0; kb < kblks; kb++) {
                int as = kb & 1;
                if (kb >= 2) mbar_wait(bAe + as*8, ((kb >> 1) & 1) ^ 1);
                mbar_expect(bAf + as*8, A_STG);
                // blobs hold 128 rows; BM=64 tile is the (mblk&1) half
                size_t aoff = ((size_t)(mblk >> 1) * kblks + kb) * 8192 + (size_t)(mblk & 1) * 4096;
                bulk_g2s(sb + as*A_STG, Ah + aoff, ABYTES, bAf + as*8);
                if (ALO)
                    bulk_g2s(sb + as*A_STG + ABYTES, Al + aoff, ABYTES, bAf + as*8);
                for (int e = 0; e < EXP; e++) {
                    int wu = kb * EXP + e, s = wu & (WS - 1);
                    if (wu >= WS) mbar_wait(bWe + s*8, ((wu / WS) & 1) ^ 1);
                    mbar_expect(bWf + s*8, WLO ? 16384 : 8192);
                    size_t woff = (((size_t)e * wnb + nblk) * kblks + kb) * 4096;
                    bulk_g2s(sb + W_OFFc + s*W_STRIDE, Wh + woff, 8192, bWf + s*8);
                    if (WLO)
                        bulk_g2s(sb + W_OFFc + s*W_STRIDE + 8192, Wl + woff, 8192, bWf + s*8);
                }
            }
        }
        return;
    }

    // ---------------- compute warps (0-3) ----------------
    uint32_t offA[2][4], offB[2][4];
#pragma unroll
    for (int i = 0; i < 2; i++)
#pragma unroll
        for (int j = 0; j < 4; j++)
            offA[i][j] = SWZ((uint32_t)((wm*32 + i*16 + (lane & 15)) * 128 + j*32 + (lane >> 4) * 16));
#pragma unroll
    for (int p = 0; p < 2; p++)
#pragma unroll
        for (int j = 0; j < 4; j++)
            offB[p][j] = SWZ((uint32_t)((wn*32 + p*16 + (lane & 15)) * 128 + j*32 + (lane >> 4) * 16));

    float acc[2][4][4];
#pragma unroll
    for (int i = 0; i < 2; i++)
#pragma unroll
        for (int n8 = 0; n8 < 4; n8++)
#pragma unroll
            for (int q = 0; q < 4; q++) acc[i][n8][q] = 0.f;

    int wu = 0;
#pragma unroll 1
    for (int kb = 0; kb < kblks; kb++) {
        int as = kb & 1;
        mbar_wait(bAf + as*8, (kb >> 1) & 1);
        const uint32_t Ab = sb + as*A_STG;
        uint32_t aH[2][4][4], aL[2][4][4];   // A fragments resident across expert loop
#pragma unroll
        for (int i = 0; i < 2; i++)
#pragma unroll
            for (int j = 0; j < 4; j++) {
                ldm_x4(aH[i][j], Ab + offA[i][j]);
                if (ALO) ldm_x4(aL[i][j], Ab + ABYTES + offA[i][j]);
            }
        if (lane == 0) mbar_arrive(bAe + as*8);
#pragma unroll 1
        for (int e = 0; e < EXP; e++) {
            int s = wu & (WS - 1);
            mbar_wait(bWf + s*8, (wu / WS) & 1);
            const uint32_t Wb = sb + W_OFFc + s*W_STRIDE;
            if (GATE) {
                float part[2][4][4];
#pragma unroll
                for (int i = 0; i < 2; i++)
#pragma unroll
                    for (int n8 = 0; n8 < 4; n8++)
#pragma unroll
                        for (int q = 0; q < 4; q++) part[i][n8][q] = 0.f;
#pragma unroll
                for (int j = 0; j < 4; j++) {
                    uint32_t b0h[4], b1h[4], b0l[4], b1l[4];
                    ldm_x4(b0h, Wb + offB[0][j]);
                    ldm_x4(b1h, Wb + offB[1][j]);
                    if (WLO) {
                        ldm_x4(b0l, Wb + 8192 + offB[0][j]);
                        ldm_x4(b1l, Wb + 8192 + offB[1][j]);
                    }
#pragma unroll
                    for (int i = 0; i < 2; i++)
#pragma unroll
                        for (int n8 = 0; n8 < 4; n8++) {
                            const uint32_t* bh = (n8 < 2) ? b0h : b1h;
                            int q = n8 & 1;
                            mma16816(part[i][n8], aH[i][j], bh[q], bh[2 + q]);
                            if (ALO) mma16816(part[i][n8], aL[i][j], bh[q], bh[2 + q]);
                            if (WLO) {
                                const uint32_t* bl = (n8 < 2) ? b0l : b1l;
                                mma16816(part[i][n8], aH[i][j], bl[q], bl[2 + q]);
                            }
                        }
                }
                if (lane == 0) mbar_arrive(bWe + s*8);
                int r0 = wm*32 + (lane >> 2);
                float g0 = gS[(r0 + 0)  * EE + e], g1 = gS[(r0 + 8)  * EE + e];
                float g2 = gS[(r0 + 16) * EE + e], g3 = gS[(r0 + 24) * EE + e];
#pragma unroll
                for (int n8 = 0; n8 < 4; n8++) {
                    acc[0][n8][0] += g0 * part[0][n8][0];
                    acc[0][n8][1] += g0 * part[0][n8][1];
                    acc[0][n8][2] += g1 * part[0][n8][2];
                    acc[0][n8][3] += g1 * part[0][n8][3];
                    acc[1][n8][0] += g2 * part[1][n8][0];
                    acc[1][n8][1] += g2 * part[1][n8][1];
                    acc[1][n8][2] += g3 * part[1][n8][2];
                    acc[1][n8][3] += g3 * part[1][n8][3];
                }
            } else {
#pragma unroll
                for (int j = 0; j < 4; j++) {
                    uint32_t b0h[4], b1h[4], b0l[4], b1l[4];
                    ldm_x4(b0h, Wb + offB[0][j]);
                    ldm_x4(b1h, Wb + offB[1][j]);
                    if (WLO) {
                        ldm_x4(b0l, Wb + 8192 + offB[0][j]);
                        ldm_x4(b1l, Wb + 8192 + offB[1][j]);
                    }
#pragma unroll
                    for (int i = 0; i < 2; i++)
#pragma unroll
                        for (int n8 = 0; n8 < 4; n8++) {
                            const uint32_t* bh = (n8 < 2) ? b0h : b1h;
                            int q = n8 & 1;
                            mma16816(acc[i][n8], aH[i][j], bh[q], bh[2 + q]);
                            if (ALO) mma16816(acc[i][n8], aL[i][j], bh[q], bh[2 + q]);
                            if (WLO) {
                                const uint32_t* bl = (n8 < 2) ? b0l : b1l;
                                mma16816(acc[i][n8], aH[i][j], bl[q], bl[2 + q]);
                            }
                        }
                }
                if (lane == 0) mbar_arrive(bWe + s*8);
            }
            wu++;
        }
    }

    // ---- epilogue: blended bias + activation + store ----
    const int rbase = wm*32 + (lane >> 2);
    const int cbase = wn*32 + (lane & 3) * 2;
#pragma unroll
    for (int i = 0; i < 2; i++) {
#pragma unroll
        for (int hf = 0; hf < 2; hf++) {
            int lr = rbase + i*16 + hf*8;
            int gr = mblk*BM + lr;
#pragma unroll
            for (int n8 = 0; n8 < 4; n8++) {
                int cl = cbase + n8*8;
                float v0 = acc[i][n8][hf*2 + 0];
                float v1 = acc[i][n8][hf*2 + 1];
                if (GATE) {
                    float s0 = 0.f, s1 = 0.f;
#pragma unroll
                    for (int e = 0; e < EXP; e++) {
                        float g = gS[lr * EE + e];
                        s0 += g * bS[e*64 + cl];
                        s1 += g * bS[e*64 + cl + 1];
                    }
                    v0 += s0; v1 += s1;
                } else { v0 += bS[cl]; v1 += bS[cl + 1]; }
                if (ACT) { v0 = elu1(v0); v1 = elu1(v1); }
                if (OUTF32) {
                    int c = nblk*64 + cl;
                    if (c < ntot)     C[(size_t)gr * ldc + c]     = v0;
                    if (c + 1 < ntot) C[(size_t)gr * ldc + c + 1] = v1;
                } else {
                    __half h0 = __float2half_rn(v0), h1 = __float2half_rn(v1);
                    int gcol = nblk*64 + cl;
                    uint32_t off = SWZ((uint32_t)((gr & 127) * 128 + (gcol & 63) * 2));
                    size_t bidx = ((size_t)(gr >> 7) * okb + (gcol >> 6)) * 8192;
                    *(__half2*)((uint8_t*)(Oh + bidx) + off) = __halves2half2(h0, h1);
                    if (OUTLO) {
                        __half l0 = __float2half_rn(v0 - __half2float(h0));
                        __half l1 = __float2half_rn(v1 - __half2float(h1));
                        *(__half2*)((uint8_t*)(Ol + bidx) + off) = __halves2half2(l0, l1);
                    }
                }
            }
        }
    }
}

// ---------------- prepack: fp32 -> fp16 (hi, optional lo), SW128-swizzled blobs ----------------
__device__ __forceinline__ void split_store(uint8_t* bh, uint8_t* bl, uint32_t sw, float4 v) {
    float vv[4] = {v.x, v.y, v.z, v.w};
    uint32_t h[4], l[4];
#pragma unroll
    for (int q = 0; q < 4; q++) {
        __half hh = __float2half_rn(vv[q]);
        h[q] = (uint32_t)__half_as_ushort(hh);
        if (bl) {
            __half ll = __float2half_rn(vv[q] - __half2float(hh));
            l[q] = (uint32_t)__half_as_ushort(ll);
        }
    }
    *(uint2*)(bh + sw) = make_uint2(h[0] | (h[1] << 16), h[2] | (h[3] << 16));
    if (bl)
        *(uint2*)(bl + sw) = make_uint2(l[0] | (l[1] << 16), l[2] | (l[3] << 16));
}

struct PWJob { const float* W; __half* Dh; __half* Dl; int N, K, nblks, kblks, blk0, cnt; };
struct PWJobs { PWJob j[6]; };

__global__ void prepack_w_all(PWJobs jobs) {
    int b = blockIdx.x;
#pragma unroll 1
    for (int ji = 0; ji < 6; ji++) {
        const PWJob& J = jobs.j[ji];
        if (b < J.blk0 || b >= J.blk0 + J.cnt) continue;
        int t = b - J.blk0;
        int kb = t % J.kblks, nb = (t / J.kblks) % J.nblks, e = t / (J.kblks * J.nblks);
        const float* src = J.W + (size_t)e * J.N * J.K;
        uint8_t* bh = (uint8_t*)(J.Dh + (size_t)t * 4096);
        uint8_t* bl = J.Dl ? (uint8_t*)(J.Dl + (size_t)t * 4096) : nullptr;
        for (int i = threadIdx.x; i < 1024; i += 256) {
            int r = i >> 4, c4 = i & 15;
            int n = nb * 64 + r, k = kb * 64 + c4 * 4;
            float4 v = make_float4(0.f, 0.f, 0.f, 0.f);
            if (n < J.N && k < J.K) v = *(const float4*)(src + (size_t)n * J.K + k);
            split_store(bh, bl, SWZ((uint32_t)(r * 128 + c4 * 8)), v);
        }
        return;
    }
}

__global__ void prepack_a_all(const float* __restrict__ x, const float* __restrict__ z) {
    int b = blockIdx.x;
    if (b < MBK * 5) {
        int kb = b % 5, mb = b / 5;
        uint8_t* bh = (uint8_t*)(g_A0h + (size_t)b * 8192);
        uint8_t* bl = (uint8_t*)(g_A0l + (size_t)b * 8192);
        for (int i = threadIdx.x; i < 2048; i += 256) {
            int r = i >> 4, c4 = i & 15;
            int row = mb * 128 + r, k = kb * 64 + c4 * 4;
            float4 v;
            if (k < D3) v = *(const float4*)(x + (size_t)row * D3 + k);
            else        v = *(const float4*)(z + (size_t)row * LZ + (k - D3));
            split_store(bh, bl, SWZ((uint32_t)(r * 128 + c4 * 8)), v);
        }
    } else {
        int mb = b - MBK * 5;
        size_t off = ((size_t)mb * 9 + 8) * 8192;
        for (int i = threadIdx.x; i < 2048; i += 256) {
            int r = i >> 4, c4 = i & 15;
            int row = mb * 128 + r, k = c4 * 4;
            float4 v = make_float4(0.f, 0.f, 0.f, 0.f);
            if (k < LZ) v = *(const float4*)(z + (size_t)row * LZ + k);
            uint32_t sw = SWZ((uint32_t)(r * 128 + c4 * 8));
            split_store((uint8_t*)(g_A1h + off), nullptr, sw, v);
            split_store((uint8_t*)(g_A2h + off), nullptr, sw, v);
        }
    }
}

// ---------------- gating logits + softmax (warp-per-row, smem-staged gW3) ----------------
__global__ void logits_softmax(const float* __restrict__ h2,
                               const float* __restrict__ gW3,
                               const float* __restrict__ gb3) {
    __shared__ float ws[8][128];
    __shared__ float bsm[8];
    int tid = threadIdx.x, lane = tid & 31, w = tid >> 5;
    for (int i = tid; i < 8 * 128; i += 256) ws[i >> 7][i & 127] = gW3[i];
    if (tid < 8) bsm[tid] = gb3[tid];
    __syncthreads();
    int row = blockIdx.x * 8 + w;
    float4 v = ((const float4*)(h2 + (size_t)row * GHD))[lane];
    float p[8];
#pragma unroll
    for (int e = 0; e < 8; e++) {
        float4 wv = ((const float4*)ws[e])[lane];
        p[e] = v.x*wv.x + v.y*wv.y + v.z*wv.z + v.w*wv.w;
    }
#pragma unroll
    for (int o = 16; o; o >>= 1)
#pragma unroll
        for (int e = 0; e < 8; e++) p[e] += __shfl_xor_sync(0xffffffffu, p[e], o);
    if (lane < 8) {
        float m = -1e30f;
#pragma unroll
        for (int e = 0; e < 8; e++) { p[e] += bsm[e]; m = fmaxf(m, p[e]); }
        float Z = 0.f;
#pragma unroll
        for (int e = 0; e < 8; e++) Z += expf(p[e] - m);
        float myp = p[0];
#pragma unroll
        for (int e = 1; e < 8; e++) myp = (lane == e) ? p[e] : myp;
        g_gate[row * 8 + lane] = expf(myp - m) / Z;
    }
}

// ---------------- host ----------------
// smem sizes: 2*A_STG + 4*W_STRIDE + 2048 + 2048 + 256
static constexpr int SMEM_G  = 2*16384 + 4*16384 + 4352;  // gating: ALO+WLO   = 102400+256
static constexpr int SMEM_L0 = 2*16384 + 4*8192  + 4352;  // L0: ALO only      =  69888
static constexpr int SMEM_L1 = 2*8192  + 4*8192  + 4352;  // L1-3: single-term =  53504

extern "C" void kernel_launch(void* const* d_in, const int* in_sizes, int n_in,
                              void* d_out, int out_size) {
    const float* x   = (const float*)d_in[0];
    const float* z   = (const float*)d_in[1];
    const float* W0  = (const float*)d_in[2];
    const float* b0  = (const float*)d_in[3];
    const float* W1  = (const float*)d_in[4];
    const float* b1  = (const float*)d_in[5];
    const float* W2  = (const float*)d_in[6];
    const float* b2  = (const float*)d_in[7];
    const float* W3  = (const float*)d_in[8];
    const float* b3  = (const float*)d_in[9];
    const float* gW1 = (const float*)d_in[10];
    const float* gb1 = (const float*)d_in[11];
    const float* gW2 = (const float*)d_in[12];
    const float* gb2 = (const float*)d_in[13];
    const float* gW3 = (const float*)d_in[14];
    const float* gb3 = (const float*)d_in[15];
    float* out = (float*)d_out;
    (void)in_sizes; (void)n_in; (void)out_size;

    __half *A0h,*A0l,*A1h,*A2h,*A3h,*G1h,*G1l;
    __half *pW0h,*pW1h,*pW2h,*pW3h,*pg1h,*pg1l,*pg2h,*pg2l;
    float *gh2, *gate;
    cudaGetSymbolAddress((void**)&A0h, g_A0h); cudaGetSymbolAddress((void**)&A0l, g_A0l);
    cudaGetSymbolAddress((void**)&A1h, g_A1h);
    cudaGetSymbolAddress((void**)&A2h, g_A2h);
    cudaGetSymbolAddress((void**)&A3h, g_A3h);
    cudaGetSymbolAddress((void**)&G1h, g_G1h); cudaGetSymbolAddress((void**)&G1l, g_G1l);
    cudaGetSymbolAddress((void**)&pW0h, g_W0h);
    cudaGetSymbolAddress((void**)&pW1h, g_W1h);
    cudaGetSymbolAddress((void**)&pW2h, g_W2h);
    cudaGetSymbolAddress((void**)&pW3h, g_W3h);
    cudaGetSymbolAddress((void**)&pg1h, g_gW1h); cudaGetSymbolAddress((void**)&pg1l, g_gW1l);
    cudaGetSymbolAddress((void**)&pg2h, g_gW2h); cudaGetSymbolAddress((void**)&pg2l, g_gW2l);
    cudaGetSymbolAddress((void**)&gh2, g_gh2); cudaGetSymbolAddress((void**)&gate, g_gate);

    cudaFuncSetAttribute(moe_gemm<1,false,true,false,true,true,true>, cudaFuncAttributeMaxDynamicSharedMemorySize, SMEM_G);
    cudaFuncSetAttribute(moe_gemm<1,false,true,true,true,true,false>, cudaFuncAttributeMaxDynamicSharedMemorySize, SMEM_G);
    cudaFuncSetAttribute(moe_gemm<8,true,true,false,false,true,false>,  cudaFuncAttributeMaxDynamicSharedMemorySize, SMEM_L0);
    cudaFuncSetAttribute(moe_gemm<8,true,true,false,false,false,false>, cudaFuncAttributeMaxDynamicSharedMemorySize, SMEM_L1);
    cudaFuncSetAttribute(moe_gemm<8,true,false,true,false,false,false>, cudaFuncAttributeMaxDynamicSharedMemorySize, SMEM_L1);

    // prepack weights (one launch; lo split only for gating weights) + inputs (one launch)
    PWJobs jobs;
    jobs.j[0] = {W0,  pW0h, nullptr, HH,  320, 8, 5, 0,    320};
    jobs.j[1] = {W1,  pW1h, nullptr, HH,  544, 8, 9, 320,  576};
    jobs.j[2] = {W2,  pW2h, nullptr, HH,  544, 8, 9, 896,  576};
    jobs.j[3] = {W3,  pW3h, nullptr, OO,  512, 2, 8, 1472, 128};
    jobs.j[4] = {gW1, pg1h, pg1l,    GHD, 320, 2, 5, 1600, 10};
    jobs.j[5] = {gW2, pg2h, pg2l,    GHD, GHD, 2, 2, 1610, 4};
    prepack_w_all<<<1614, 256>>>(jobs);
    prepack_a_all<<<MBK*5 + MBK, 256>>>(x, z);

    // gating MLP (full 3-term precision: softmax amplifies gate errors)
    moe_gemm<1,false,true,false,true,true,true><<<dim3(2, 64), 160, SMEM_G>>>(
        A0h, A0l, 5, pg1h, pg1l, 2, gb1, nullptr, GHD, G1h, G1l, 2, nullptr, 0);
    moe_gemm<1,false,true,true,true,true,false><<<dim3(2, 64), 160, SMEM_G>>>(
        G1h, G1l, 2, pg2h, pg2l, 2, gb2, nullptr, GHD, nullptr, nullptr, 0, gh2, GHD);
    logits_softmax<<<BB/8, 256>>>(gh2, gW3, gb3);

    // blended expert layers: L0 2-term (A hi/lo), L1-L3 single-term fp16
    moe_gemm<8,true,true,false,false,true,false><<<dim3(8, 64), 160, SMEM_L0>>>(
        A0h, A0l, 5, pW0h, nullptr, 8, b0, gate, HH, A1h, nullptr, 9, nullptr, 0);
    moe_gemm<8,true,true,false,false,false,false><<<dim3(8, 64), 160, SMEM_L1>>>(
        A1h, nullptr, 9, pW1h, nullptr, 8, b1, gate, HH, A2h, nullptr, 9, nullptr, 0);
    moe_gemm<8,true,true,false,false,false,false><<<dim3(8, 64), 160, SMEM_L1>>>(
        A2h, nullptr, 9, pW2h, nullptr, 8, b2, gate, HH, A3h, nullptr, 8, nullptr, 0);
    moe_gemm<8,true,false,true,false,false,false><<<dim3(2, 64), 160, SMEM_L1>>>(
        A3h, nullptr, 8, pW3h, nullptr, 2, b3, gate, OO, nullptr, nullptr, 0, out, OO);
}